// round 2
// baseline (speedup 1.0000x reference)
#include <cuda_runtime.h>
#include <math.h>

#define NSEQ 8192
#define DIM 512
#define HEADS 8
#define DH 64
#define FFD 2048
#define LLMD 4096

// ---------------- static scratch (no runtime allocation allowed) ----------------
__device__ float g_X[NSEQ * DIM];
__device__ float g_H[NSEQ * DIM];
__device__ float g_Q[NSEQ * DIM];
__device__ float g_K[NSEQ * DIM];
__device__ float g_V[NSEQ * DIM];
__device__ float g_O[NSEQ * DIM];
__device__ float g_G[NSEQ * FFD];
__device__ float g_pbuf[64 * DIM];
__device__ float g_colmax[DIM];
__device__ float g_colinv[DIM];
__device__ float g_ctx[HEADS * DH * DH];

// ---------------- positional encoding add ----------------
__global__ void pe_kernel(const float* __restrict__ x, float* __restrict__ X) {
    int i = blockIdx.x * 256 + threadIdx.x;      // NSEQ*DIM threads
    int n = i >> 9;                               // /512
    int d = i & 511;
    int e = d & ~1;                               // even exponent index
    float divv = expf((float)e * (-9.210340371976184f / 512.0f));
    float ang = (float)n * divv;
    float pe = (d & 1) ? cosf(ang) : sinf(ang);
    X[i] = x[i] + pe;
}

// ---------------- layernorm: one block (128 thr) per row ----------------
__global__ void ln_kernel(const float* __restrict__ X, const float* __restrict__ g,
                          const float* __restrict__ b, float* __restrict__ H) {
    int row = blockIdx.x;
    int t = threadIdx.x;  // 0..127, 4 floats each
    const float4* xr = (const float4*)(X + row * DIM);
    float4 v = xr[t];
    float s = v.x + v.y + v.z + v.w;
    float s2 = v.x * v.x + v.y * v.y + v.z * v.z + v.w * v.w;
#pragma unroll
    for (int o = 16; o; o >>= 1) {
        s  += __shfl_xor_sync(0xffffffffu, s, o);
        s2 += __shfl_xor_sync(0xffffffffu, s2, o);
    }
    __shared__ float ss[4], ss2[4];
    if ((t & 31) == 0) { ss[t >> 5] = s; ss2[t >> 5] = s2; }
    __syncthreads();
    s  = ss[0] + ss[1] + ss[2] + ss[3];
    s2 = ss2[0] + ss2[1] + ss2[2] + ss2[3];
    float mu  = s * (1.0f / DIM);
    float var = s2 * (1.0f / DIM) - mu * mu;
    float rstd = rsqrtf(var + 1e-5f);
    float4 gg = ((const float4*)g)[t];
    float4 bb = ((const float4*)b)[t];
    float4 o4;
    o4.x = (v.x - mu) * rstd * gg.x + bb.x;
    o4.y = (v.y - mu) * rstd * gg.y + bb.y;
    o4.z = (v.z - mu) * rstd * gg.z + bb.z;
    o4.w = (v.w - mu) * rstd * gg.w + bb.w;
    ((float4*)(H + row * DIM))[t] = o4;
}

// ---------------- generic SGEMM 128x128x8, 256 thr, 8x8 microtile ----------------
// EPI: 0=none, 1=+bias, 2=+bias+residual, 3=+bias then exact GELU
__device__ __forceinline__ float gelu_exact(float v) {
    return 0.5f * v * (1.0f + erff(v * 0.70710678118654752f));
}

template <int EPI>
__global__ void __launch_bounds__(256, 2)
gemm_kernel(const float* __restrict__ A, const float* __restrict__ B,
            float* __restrict__ C, const float* __restrict__ bias,
            const float* __restrict__ R, int M, int N, int K) {
    __shared__ float As[8][128];
    __shared__ float Bs[8][128];
    int tid = threadIdx.x;
    int cBase = blockIdx.x * 128;
    int rBase = blockIdx.y * 128;
    int tx = tid & 15;       // column microtile
    int ty = tid >> 4;       // row microtile
    int arow = tid >> 1, ac4 = (tid & 1) * 4;
    int brow = tid >> 5, bc4 = (tid & 31) * 4;
    const float* Aptr = A + (rBase + arow) * K + ac4;
    const float* Bptr = B + brow * N + cBase + bc4;

    float acc[8][8];
#pragma unroll
    for (int i = 0; i < 8; i++)
#pragma unroll
        for (int j = 0; j < 8; j++) acc[i][j] = 0.0f;

    for (int k0 = 0; k0 < K; k0 += 8) {
        float4 av = *(const float4*)(Aptr + k0);
        float4 bv = *(const float4*)(Bptr + k0 * N);
        As[ac4 + 0][arow] = av.x;
        As[ac4 + 1][arow] = av.y;
        As[ac4 + 2][arow] = av.z;
        As[ac4 + 3][arow] = av.w;
        *(float4*)&Bs[brow][bc4] = bv;
        __syncthreads();
#pragma unroll
        for (int kk = 0; kk < 8; kk++) {
            float4 a0 = *(float4*)&As[kk][ty * 8];
            float4 a1 = *(float4*)&As[kk][ty * 8 + 4];
            float4 b0 = *(float4*)&Bs[kk][tx * 8];
            float4 b1 = *(float4*)&Bs[kk][tx * 8 + 4];
            float ar[8] = {a0.x, a0.y, a0.z, a0.w, a1.x, a1.y, a1.z, a1.w};
            float br[8] = {b0.x, b0.y, b0.z, b0.w, b1.x, b1.y, b1.z, b1.w};
#pragma unroll
            for (int i = 0; i < 8; i++)
#pragma unroll
                for (int j = 0; j < 8; j++) acc[i][j] += ar[i] * br[j];
        }
        __syncthreads();
    }

    int col0 = cBase + tx * 8;
#pragma unroll
    for (int i = 0; i < 8; i++) {
        int row = rBase + ty * 8 + i;
        float* crow = C + (size_t)row * N + col0;
#pragma unroll
        for (int j = 0; j < 8; j++) {
            float v = acc[i][j];
            if (EPI >= 1) v += bias[col0 + j];
            if (EPI == 2) v += R[(size_t)row * N + col0 + j];
            if (EPI == 3) v = gelu_exact(v);
            crow[j] = v;
        }
    }
}

// ---------------- q softmax over feature dim (per head), * DH^-0.5 ----------------
__global__ void qsoftmax_kernel(float* __restrict__ Q) {
    int row = blockIdx.x;
    int wid = threadIdx.x >> 5;   // head
    int lane = threadIdx.x & 31;
    float2* p = (float2*)(Q + row * DIM + wid * DH) + lane;
    float2 v = *p;
    float m = fmaxf(v.x, v.y);
#pragma unroll
    for (int o = 16; o; o >>= 1) m = fmaxf(m, __shfl_xor_sync(0xffffffffu, m, o));
    float e0 = __expf(v.x - m), e1 = __expf(v.y - m);
    float s = e0 + e1;
#pragma unroll
    for (int o = 16; o; o >>= 1) s += __shfl_xor_sync(0xffffffffu, s, o);
    float inv = 0.125f / s;   // scale = DH^-0.5 = 0.125
    v.x = e0 * inv;
    v.y = e1 * inv;
    *p = v;
}

// ---------------- k column softmax (over sequence) ----------------
__global__ void kcolmax_kernel(const float* __restrict__ Kb, float* __restrict__ pmax) {
    int c = threadIdx.x;           // 512 threads = columns
    int chunk = blockIdx.x;        // 64 chunks of 128 rows
    const float* p = Kb + chunk * 128 * DIM + c;
    float m = -1e30f;
#pragma unroll 4
    for (int r = 0; r < 128; r++) m = fmaxf(m, p[r * DIM]);
    pmax[chunk * DIM + c] = m;
}

__global__ void kcolmax_reduce(const float* __restrict__ pmax, float* __restrict__ colmax) {
    int c = threadIdx.x;
    float m = -1e30f;
#pragma unroll 8
    for (int i = 0; i < 64; i++) m = fmaxf(m, pmax[i * DIM + c]);
    colmax[c] = m;
}

__global__ void kexp_kernel(float* __restrict__ Kb, const float* __restrict__ colmax,
                            float* __restrict__ psum) {
    int c = threadIdx.x;
    int chunk = blockIdx.x;
    float m = colmax[c];
    float* p = Kb + chunk * 128 * DIM + c;
    float s = 0.0f;
#pragma unroll 4
    for (int r = 0; r < 128; r++) {
        float e = __expf(p[r * DIM] - m);
        p[r * DIM] = e;
        s += e;
    }
    psum[chunk * DIM + c] = s;
}

__global__ void kcolsum_reduce(const float* __restrict__ psum, float* __restrict__ colinv) {
    int c = threadIdx.x;
    float s = 0.0f;
#pragma unroll 8
    for (int i = 0; i < 64; i++) s += psum[i * DIM + c];
    colinv[c] = 1.0f / s;
}

// ---------------- ctx = E^T V per head (block-diagonal 64x64), chunked + atomics ----------------
__global__ void ctx_zero_kernel(float* __restrict__ ctx) {
    ctx[blockIdx.x * 256 + threadIdx.x] = 0.0f;
}

__global__ void __launch_bounds__(256)
ctx_kernel(const float* __restrict__ E, const float* __restrict__ V, float* __restrict__ ctx) {
    int h = blockIdx.x;       // head
    int chunk = blockIdx.y;   // 16 chunks of 512 rows
    __shared__ float Es[32][64];
    __shared__ float Vs[32][64];
    int tid = threadIdx.x;
    int tx = tid & 15, ty = tid >> 4;
    float acc[4][4] = {};
    int rbase = chunk * 512;
    for (int r0 = 0; r0 < 512; r0 += 32) {
#pragma unroll
        for (int ld = 0; ld < 2; ld++) {
            int ii = tid + ld * 256;           // 512 float4 loads
            int rr = ii >> 4, c4 = (ii & 15) * 4;
            const float* eb = E + (rbase + r0 + rr) * DIM + h * DH + c4;
            const float* vb = V + (rbase + r0 + rr) * DIM + h * DH + c4;
            *(float4*)&Es[rr][c4] = *(const float4*)eb;
            *(float4*)&Vs[rr][c4] = *(const float4*)vb;
        }
        __syncthreads();
#pragma unroll
        for (int r = 0; r < 32; r++) {
            float4 a4 = *(float4*)&Es[r][ty * 4];
            float4 b4 = *(float4*)&Vs[r][tx * 4];
            float a[4] = {a4.x, a4.y, a4.z, a4.w};
            float b[4] = {b4.x, b4.y, b4.z, b4.w};
#pragma unroll
            for (int i = 0; i < 4; i++)
#pragma unroll
                for (int j = 0; j < 4; j++) acc[i][j] += a[i] * b[j];
        }
        __syncthreads();
    }
#pragma unroll
    for (int i = 0; i < 4; i++)
#pragma unroll
        for (int j = 0; j < 4; j++)
            atomicAdd(&ctx[h * (DH * DH) + (ty * 4 + i) * DH + tx * 4 + j], acc[i][j]);
}

__global__ void ctx_fix_kernel(float* __restrict__ ctx, const float* __restrict__ colinv) {
    int i = blockIdx.x * 256 + threadIdx.x;    // 8*64*64 = 32768
    int h = i >> 12;
    int d = (i >> 6) & 63;
    ctx[i] *= colinv[h * DH + d];
}

// ---------------- o = q_sm @ ctx per head ----------------
__global__ void __launch_bounds__(256)
attn_o_kernel(const float* __restrict__ Q, const float* __restrict__ ctx,
              float* __restrict__ O) {
    int nt = blockIdx.x;   // 128 tiles of 64 rows
    int h = blockIdx.y;
    __shared__ float Cs[64][64];
    __shared__ float Qs[64][64];
    int tid = threadIdx.x;
#pragma unroll
    for (int ld = 0; ld < 4; ld++) {
        int ii = tid + ld * 256;              // 1024 float4 loads per matrix
        int rr = ii >> 4, c4 = (ii & 15) * 4;
        *(float4*)&Cs[rr][c4] = *(const float4*)(ctx + h * (DH * DH) + rr * DH + c4);
        *(float4*)&Qs[rr][c4] = *(const float4*)(Q + (nt * 64 + rr) * DIM + h * DH + c4);
    }
    __syncthreads();
    int tx = tid & 15, ty = tid >> 4;
    float acc[4][4] = {};
#pragma unroll 8
    for (int d = 0; d < 64; d++) {
        float a[4];
#pragma unroll
        for (int i = 0; i < 4; i++) a[i] = Qs[ty * 4 + i][d];  // 2-way broadcast within warp
        float4 b4 = *(float4*)&Cs[d][tx * 4];
        float b[4] = {b4.x, b4.y, b4.z, b4.w};
#pragma unroll
        for (int i = 0; i < 4; i++)
#pragma unroll
            for (int j = 0; j < 4; j++) acc[i][j] += a[i] * b[j];
    }
#pragma unroll
    for (int i = 0; i < 4; i++) {
        float4 o4 = make_float4(acc[i][0], acc[i][1], acc[i][2], acc[i][3]);
        *(float4*)(O + (nt * 64 + ty * 4 + i) * DIM + h * DH + tx * 4) = o4;
    }
}

// ---------------- host orchestration ----------------
extern "C" void kernel_launch(void* const* d_in, const int* in_sizes, int n_in,
                              void* d_out, int out_size) {
    const float* x      = (const float*)d_in[0];
    const float* ln1_g  = (const float*)d_in[1];
    const float* ln1_b  = (const float*)d_in[2];
    const float* Wq     = (const float*)d_in[3];
    const float* Wk     = (const float*)d_in[4];
    const float* Wv     = (const float*)d_in[5];
    const float* Wo     = (const float*)d_in[6];
    const float* bo     = (const float*)d_in[7];
    const float* ln2_g  = (const float*)d_in[8];
    const float* ln2_b  = (const float*)d_in[9];
    const float* W1     = (const float*)d_in[10];
    const float* b1     = (const float*)d_in[11];
    const float* W2     = (const float*)d_in[12];
    const float* b2     = (const float*)d_in[13];
    const float* projW  = (const float*)d_in[14];
    const float* projb  = (const float*)d_in[15];
    float* out = (float*)d_out;

    float *X, *H, *Q, *K, *V, *O, *G, *pbuf, *colmax, *colinv, *ctx;
    cudaGetSymbolAddress((void**)&X, g_X);
    cudaGetSymbolAddress((void**)&H, g_H);
    cudaGetSymbolAddress((void**)&Q, g_Q);
    cudaGetSymbolAddress((void**)&K, g_K);
    cudaGetSymbolAddress((void**)&V, g_V);
    cudaGetSymbolAddress((void**)&O, g_O);
    cudaGetSymbolAddress((void**)&G, g_G);
    cudaGetSymbolAddress((void**)&pbuf, g_pbuf);
    cudaGetSymbolAddress((void**)&colmax, g_colmax);
    cudaGetSymbolAddress((void**)&colinv, g_colinv);
    cudaGetSymbolAddress((void**)&ctx, g_ctx);

    pe_kernel<<<NSEQ * DIM / 256, 256>>>(x, X);

    dim3 gDD(DIM / 128, NSEQ / 128);     // M x 512 GEMMs
    dim3 gFF(FFD / 128, NSEQ / 128);     // M x 2048
    dim3 gLL(LLMD / 128, NSEQ / 128);    // M x 4096
    dim3 gctx(HEADS, 16);
    dim3 go(NSEQ / 64, HEADS);

    for (int l = 0; l < 2; l++) {
        const float* wq = Wq + l * DIM * DIM;
        const float* wk = Wk + l * DIM * DIM;
        const float* wv = Wv + l * DIM * DIM;
        const float* wo = Wo + l * DIM * DIM;
        const float* w1 = W1 + l * DIM * FFD;
        const float* w2 = W2 + l * FFD * DIM;

        ln_kernel<<<NSEQ, 128>>>(X, ln1_g + l * DIM, ln1_b + l * DIM, H);
        gemm_kernel<0><<<gDD, 256>>>(H, wq, Q, nullptr, nullptr, NSEQ, DIM, DIM);
        gemm_kernel<0><<<gDD, 256>>>(H, wk, K, nullptr, nullptr, NSEQ, DIM, DIM);
        gemm_kernel<0><<<gDD, 256>>>(H, wv, V, nullptr, nullptr, NSEQ, DIM, DIM);

        qsoftmax_kernel<<<NSEQ, 256>>>(Q);

        kcolmax_kernel<<<64, 512>>>(K, pbuf);
        kcolmax_reduce<<<1, 512>>>(pbuf, colmax);
        kexp_kernel<<<64, 512>>>(K, colmax, pbuf);
        kcolsum_reduce<<<1, 512>>>(pbuf, colinv);

        ctx_zero_kernel<<<HEADS * DH * DH / 256, 256>>>(ctx);
        ctx_kernel<<<gctx, 256>>>(K, V, ctx);
        ctx_fix_kernel<<<HEADS * DH * DH / 256, 256>>>(ctx, colinv);

        attn_o_kernel<<<go, 256>>>(Q, ctx, O);

        gemm_kernel<2><<<gDD, 256>>>(O, wo, X, bo + l * DIM, X, NSEQ, DIM, DIM);

        ln_kernel<<<NSEQ, 128>>>(X, ln2_g + l * DIM, ln2_b + l * DIM, H);
        gemm_kernel<3><<<gFF, 256>>>(H, w1, G, b1 + l * FFD, nullptr, NSEQ, FFD, DIM);
        gemm_kernel<2><<<gDD, 256>>>(G, w2, X, b2 + l * DIM, X, NSEQ, DIM, FFD);
    }

    gemm_kernel<1><<<gLL, 256>>>(X, projW, out, projb, nullptr, NSEQ, LLMD, DIM);
}

// round 7
// speedup vs baseline: 2.0756x; 2.0756x over previous
#include <cuda_runtime.h>
#include <cuda_fp16.h>
#include <math.h>
#include <stdint.h>

#define NSEQ 8192
#define DIM 512
#define HEADS 8
#define DH 64
#define FFD 2048
#define LLMD 4096

#define PADK 40                         // halves per smem row (32 data + 8 pad)
#define ARRB (128 * PADK * 2)           // bytes per array per stage = 10240
#define STGB (4 * ARRB)                 // bytes per stage = 40960
#define NSTAGE 3
#define GEMM_SMEM (NSTAGE * STGB)       // 122880

__device__ __forceinline__ uint32_t smem_to_u32(const void* p) {
    uint32_t a;
    asm("{ .reg .u64 t; cvta.to.shared.u64 t, %1; cvt.u32.u64 %0, t; }" : "=r"(a) : "l"(p));
    return a;
}
#define CP_ASYNC16(sp, gp) \
    asm volatile("cp.async.cg.shared.global [%0], [%1], 16;" :: "r"(sp), "l"(gp))
#define CP_COMMIT() asm volatile("cp.async.commit_group;" ::: "memory")
#define CP_WAIT1()  asm volatile("cp.async.wait_group 1;" ::: "memory")
#define LDSM4(r0, r1, r2, r3, a) \
    asm volatile("ldmatrix.sync.aligned.m8n8.x4.shared.b16 {%0,%1,%2,%3}, [%4];" \
        : "=r"(r0), "=r"(r1), "=r"(r2), "=r"(r3) : "r"(a))
#define MMA16816(c0, c1, c2, c3, a0, a1, a2, a3, b0, b1) \
    asm volatile("mma.sync.aligned.m16n8k16.row.col.f32.f16.f16.f32 " \
        "{%0,%1,%2,%3},{%4,%5,%6,%7},{%8,%9},{%0,%1,%2,%3};" \
        : "+f"(c0), "+f"(c1), "+f"(c2), "+f"(c3) \
        : "r"(a0), "r"(a1), "r"(a2), "r"(a3), "r"(b0), "r"(b1))

__device__ __forceinline__ void hsplit(float v, __half& hi, __half& lo) {
    hi = __float2half_rn(v);
    lo = __float2half_rn(v - __half2float(hi));
}
__device__ __forceinline__ float gelu_exact(float v) {
    return 0.5f * v * (1.0f + erff(v * 0.70710678118654752f));
}

// ================= static scratch =================
__device__ float g_X[NSEQ * DIM];
__device__ float g_Q[NSEQ * DIM];
__device__ float g_K[NSEQ * DIM];
__device__ float g_V[NSEQ * DIM];
__device__ __half g_Hhi[NSEQ * DIM];
__device__ __half g_Hlo[NSEQ * DIM];
__device__ __half g_Ghi[NSEQ * FFD];
__device__ __half g_Glo[NSEQ * FFD];
#define WTOT 8388608
__device__ __half g_Whi[WTOT];
__device__ __half g_Wlo[WTOT];
__device__ float g_pbuf[64 * DIM];
__device__ float g_colmax[DIM];
__device__ float g_colinv[DIM];
__device__ float g_ctx[HEADS * DH * DH];

#define WOFF_QKVO(l, j) ((size_t)((l) * 4 + (j)) * 262144)
#define WOFF_W1(l) (2097152 + (size_t)(l) * 1048576)
#define WOFF_W2(l) (4194304 + (size_t)(l) * 1048576)
#define WOFF_PJ 6291456

// ================= weight transpose + fp16 split =================
__global__ void wsplit_kernel(const float* __restrict__ Wq, const float* __restrict__ Wk,
                              const float* __restrict__ Wv, const float* __restrict__ Wo,
                              const float* __restrict__ W1, const float* __restrict__ W2,
                              const float* __restrict__ Pj,
                              __half* __restrict__ Whi, __half* __restrict__ Wlo) {
    __shared__ float s[32][33];
    int b = blockIdx.x;
    const float* src;
    size_t dst;
    int K, N, tile;
    if (b < 2048) {
        int m = b >> 8, l = m >> 2, j = m & 3;
        tile = b & 255;
        const float* ptrs[4] = {Wq, Wk, Wv, Wo};
        src = ptrs[j] + (size_t)l * 262144;
        K = 512; N = 512; dst = (size_t)m * 262144;
    } else if (b < 4096) {
        int i = b - 2048, l = i >> 10;
        tile = i & 1023;
        src = W1 + (size_t)l * 1048576;
        K = 512; N = 2048; dst = WOFF_W1(l);
    } else if (b < 6144) {
        int i = b - 4096, l = i >> 10;
        tile = i & 1023;
        src = W2 + (size_t)l * 1048576;
        K = 2048; N = 512; dst = WOFF_W2(l);
    } else {
        tile = b - 6144;
        src = Pj;
        K = 512; N = 4096; dst = WOFF_PJ;
    }
    int tpr = N >> 5;
    int n0 = (tile % tpr) * 32, k0 = (tile / tpr) * 32;
    int c = threadIdx.x & 31, r0 = threadIdx.x >> 5;
#pragma unroll
    for (int i = 0; i < 4; i++) {
        int r = r0 + i * 8;
        s[r][c] = src[(size_t)(k0 + r) * N + n0 + c];
    }
    __syncthreads();
#pragma unroll
    for (int i = 0; i < 4; i++) {
        int r = r0 + i * 8;
        __half hi, lo;
        hsplit(s[c][r], hi, lo);
        size_t o = dst + (size_t)(n0 + r) * K + k0 + c;
        Whi[o] = hi;
        Wlo[o] = lo;
    }
}

// ================= HMMA GEMM: C[M,N] = A[M,K] * B[N,K]^T, fp16x2 split =================
// EPI: 0 fp32, 1 +bias fp32, 2 +bias+residual fp32, 3 +bias+GELU -> fp16 hi/lo
template <int EPI>
__global__ void __launch_bounds__(256)
hgemm(const __half* __restrict__ Ahg, const __half* __restrict__ Alg,
      const __half* __restrict__ Bhg, const __half* __restrict__ Blg,
      float* __restrict__ C, __half* __restrict__ Chi, __half* __restrict__ Clo,
      const float* __restrict__ bias, const float* __restrict__ R, int Ktot, int N) {
    extern __shared__ char smem[];
    const int tid = threadIdx.x, lane = tid & 31, wid = tid >> 5;
    const int warpM = (wid & 1) * 64, warpN = (wid >> 1) * 32;
    const int rBase = blockIdx.y * 128, cBase = blockIdx.x * 128;
    const int nch = Ktot >> 5;
    const uint32_t sbase = smem_to_u32(smem);

    const int ldrow = tid >> 2, ldch = tid & 3;

    auto issue_load = [&](int chunk, int stg) {
        uint32_t sb = sbase + stg * STGB;
        int k0 = chunk * 32;
#pragma unroll
        for (int i = 0; i < 8; i++) {
            const int arr = i >> 1;
            int row = ((i & 1) << 6) + ldrow;
            const __half* gp;
            if (arr == 0)      gp = Ahg + (size_t)(rBase + row) * Ktot;
            else if (arr == 1) gp = Alg + (size_t)(rBase + row) * Ktot;
            else if (arr == 2) gp = Bhg + (size_t)(cBase + row) * Ktot;
            else               gp = Blg + (size_t)(cBase + row) * Ktot;
            gp += k0 + ldch * 8;
            uint32_t sp = sb + arr * ARRB + (uint32_t)((row * PADK + ldch * 8) * 2);
            CP_ASYNC16(sp, gp);
        }
        CP_COMMIT();
    };

    // ldmatrix lane offsets: canonical &T[lane%16][(lane/16)*8]
    const int rr = lane & 7, tt = (lane >> 3) & 1, kp = (lane >> 4) * 8;
    uint32_t offA[4], offB[2];
#pragma unroll
    for (int mt = 0; mt < 4; mt++)
        offA[mt] = (uint32_t)(((warpM + mt * 16 + tt * 8 + rr) * PADK + kp) * 2);
#pragma unroll
    for (int p = 0; p < 2; p++)
        offB[p] = (uint32_t)(((warpN + p * 16 + tt * 8 + rr) * PADK + kp) * 2);

    float acc[4][4][4];
#pragma unroll
    for (int mt = 0; mt < 4; mt++)
#pragma unroll
        for (int nt = 0; nt < 4; nt++)
#pragma unroll
            for (int u = 0; u < 4; u++) acc[mt][nt][u] = 0.0f;

    issue_load(0, 0);
    issue_load(1, 1);

    for (int c = 0; c < nch; c++) {
        CP_WAIT1();
        __syncthreads();
        if (c + 2 < nch) issue_load(c + 2, (c + 2) % NSTAGE);
        else CP_COMMIT();   // keep committed-group count invariant for CP_WAIT1 in tail iters
        uint32_t sb = sbase + (c % NSTAGE) * STGB;
#pragma unroll
        for (int ks = 0; ks < 2; ks++) {
            uint32_t ah[4][4], al[4][4], bh[2][4], bl[2][4];
#pragma unroll
            for (int mt = 0; mt < 4; mt++)
                LDSM4(ah[mt][0], ah[mt][1], ah[mt][2], ah[mt][3], sb + offA[mt] + ks * 32);
#pragma unroll
            for (int p = 0; p < 2; p++)
                LDSM4(bh[p][0], bh[p][1], bh[p][2], bh[p][3], sb + 2 * ARRB + offB[p] + ks * 32);
#pragma unroll
            for (int mt = 0; mt < 4; mt++)
#pragma unroll
                for (int nt = 0; nt < 4; nt++)
                    MMA16816(acc[mt][nt][0], acc[mt][nt][1], acc[mt][nt][2], acc[mt][nt][3],
                             ah[mt][0], ah[mt][1], ah[mt][2], ah[mt][3],
                             bh[nt >> 1][nt & 1], bh[nt >> 1][2 + (nt & 1)]);
#pragma unroll
            for (int p = 0; p < 2; p++)
                LDSM4(bl[p][0], bl[p][1], bl[p][2], bl[p][3], sb + 3 * ARRB + offB[p] + ks * 32);
#pragma unroll
            for (int mt = 0; mt < 4; mt++)
#pragma unroll
                for (int nt = 0; nt < 4; nt++)
                    MMA16816(acc[mt][nt][0], acc[mt][nt][1], acc[mt][nt][2], acc[mt][nt][3],
                             ah[mt][0], ah[mt][1], ah[mt][2], ah[mt][3],
                             bl[nt >> 1][nt & 1], bl[nt >> 1][2 + (nt & 1)]);
#pragma unroll
            for (int mt = 0; mt < 4; mt++)
                LDSM4(al[mt][0], al[mt][1], al[mt][2], al[mt][3], sb + ARRB + offA[mt] + ks * 32);
#pragma unroll
            for (int mt = 0; mt < 4; mt++)
#pragma unroll
                for (int nt = 0; nt < 4; nt++)
                    MMA16816(acc[mt][nt][0], acc[mt][nt][1], acc[mt][nt][2], acc[mt][nt][3],
                             al[mt][0], al[mt][1], al[mt][2], al[mt][3],
                             bh[nt >> 1][nt & 1], bh[nt >> 1][2 + (nt & 1)]);
        }
    }

    // epilogue
#pragma unroll
    for (int mt = 0; mt < 4; mt++) {
#pragma unroll
        for (int nt = 0; nt < 4; nt++) {
            int row = rBase + warpM + mt * 16 + (lane >> 2);
            int col = cBase + warpN + nt * 8 + (lane & 3) * 2;
#pragma unroll
            for (int h = 0; h < 2; h++) {
                int r = row + h * 8;
                float v0 = acc[mt][nt][h * 2 + 0];
                float v1 = acc[mt][nt][h * 2 + 1];
                if (EPI >= 1) { v0 += bias[col]; v1 += bias[col + 1]; }
                if (EPI == 2) {
                    v0 += R[(size_t)r * N + col];
                    v1 += R[(size_t)r * N + col + 1];
                }
                if (EPI == 3) {
                    v0 = gelu_exact(v0);
                    v1 = gelu_exact(v1);
                    __half h0, l0, h1, l1;
                    hsplit(v0, h0, l0);
                    hsplit(v1, h1, l1);
                    *(__half2*)&Chi[(size_t)r * N + col] = __halves2half2(h0, h1);
                    *(__half2*)&Clo[(size_t)r * N + col] = __halves2half2(l0, l1);
                } else {
                    float2 f2 = make_float2(v0, v1);
                    *(float2*)&C[(size_t)r * N + col] = f2;
                }
            }
        }
    }
}

// ================= elementwise / attention =================
__global__ void pe_kernel(const float* __restrict__ x, float* __restrict__ X) {
    int i = blockIdx.x * 256 + threadIdx.x;
    int n = i >> 9, d = i & 511, e = d & ~1;
    float divv = expf((float)e * (-9.210340371976184f / 512.0f));
    float ang = (float)n * divv;
    float pe = (d & 1) ? cosf(ang) : sinf(ang);
    X[i] = x[i] + pe;
}

__global__ void ln_kernel(const float* __restrict__ X, const float* __restrict__ g,
                          const float* __restrict__ b,
                          __half* __restrict__ Hhi, __half* __restrict__ Hlo) {
    int row = blockIdx.x;
    int t = threadIdx.x;
    float4 v = ((const float4*)(X + row * DIM))[t];
    float s = v.x + v.y + v.z + v.w;
    float s2 = v.x * v.x + v.y * v.y + v.z * v.z + v.w * v.w;
#pragma unroll
    for (int o = 16; o; o >>= 1) {
        s += __shfl_xor_sync(0xffffffffu, s, o);
        s2 += __shfl_xor_sync(0xffffffffu, s2, o);
    }
    __shared__ float ss[4], ss2[4];
    if ((t & 31) == 0) { ss[t >> 5] = s; ss2[t >> 5] = s2; }
    __syncthreads();
    s = ss[0] + ss[1] + ss[2] + ss[3];
    s2 = ss2[0] + ss2[1] + ss2[2] + ss2[3];
    float mu = s * (1.0f / DIM);
    float var = s2 * (1.0f / DIM) - mu * mu;
    float rstd = rsqrtf(var + 1e-5f);
    float4 gg = ((const float4*)g)[t];
    float4 bb = ((const float4*)b)[t];
    float o0 = (v.x - mu) * rstd * gg.x + bb.x;
    float o1 = (v.y - mu) * rstd * gg.y + bb.y;
    float o2 = (v.z - mu) * rstd * gg.z + bb.z;
    float o3 = (v.w - mu) * rstd * gg.w + bb.w;
    __half h0, l0, h1, l1, h2, l2, h3, l3;
    hsplit(o0, h0, l0); hsplit(o1, h1, l1); hsplit(o2, h2, l2); hsplit(o3, h3, l3);
    __half2 ph[2] = {__halves2half2(h0, h1), __halves2half2(h2, h3)};
    __half2 pl[2] = {__halves2half2(l0, l1), __halves2half2(l2, l3)};
    *(uint2*)&Hhi[row * DIM + t * 4] = *(uint2*)ph;
    *(uint2*)&Hlo[row * DIM + t * 4] = *(uint2*)pl;
}

__global__ void split_kernel(const float* __restrict__ X,
                             __half* __restrict__ Hhi, __half* __restrict__ Hlo) {
    int i = blockIdx.x * 256 + threadIdx.x;
    float4 v = ((const float4*)X)[i];
    __half h0, l0, h1, l1, h2, l2, h3, l3;
    hsplit(v.x, h0, l0); hsplit(v.y, h1, l1); hsplit(v.z, h2, l2); hsplit(v.w, h3, l3);
    __half2 ph[2] = {__halves2half2(h0, h1), __halves2half2(h2, h3)};
    __half2 pl[2] = {__halves2half2(l0, l1), __halves2half2(l2, l3)};
    *(uint2*)&Hhi[i * 4] = *(uint2*)ph;
    *(uint2*)&Hlo[i * 4] = *(uint2*)pl;
}

__global__ void qsoftmax_kernel(float* __restrict__ Q) {
    int row = blockIdx.x;
    int wid = threadIdx.x >> 5, lane = threadIdx.x & 31;
    float2* p = (float2*)(Q + row * DIM + wid * DH) + lane;
    float2 v = *p;
    float m = fmaxf(v.x, v.y);
#pragma unroll
    for (int o = 16; o; o >>= 1) m = fmaxf(m, __shfl_xor_sync(0xffffffffu, m, o));
    float e0 = __expf(v.x - m), e1 = __expf(v.y - m);
    float s = e0 + e1;
#pragma unroll
    for (int o = 16; o; o >>= 1) s += __shfl_xor_sync(0xffffffffu, s, o);
    float inv = 0.125f / s;
    v.x = e0 * inv;
    v.y = e1 * inv;
    *p = v;
}

__global__ void kcolmax_kernel(const float* __restrict__ Kb, float* __restrict__ pmax) {
    int c = threadIdx.x, chunk = blockIdx.x;
    const float* p = Kb + chunk * 128 * DIM + c;
    float m = -1e30f;
#pragma unroll 4
    for (int r = 0; r < 128; r++) m = fmaxf(m, p[r * DIM]);
    pmax[chunk * DIM + c] = m;
}
__global__ void kcolmax_reduce(const float* __restrict__ pmax, float* __restrict__ colmax) {
    int c = threadIdx.x;
    float m = -1e30f;
#pragma unroll 8
    for (int i = 0; i < 64; i++) m = fmaxf(m, pmax[i * DIM + c]);
    colmax[c] = m;
}
__global__ void kexp_kernel(float* __restrict__ Kb, const float* __restrict__ colmax,
                            float* __restrict__ psum) {
    int c = threadIdx.x, chunk = blockIdx.x;
    float m = colmax[c];
    float* p = Kb + chunk * 128 * DIM + c;
    float s = 0.0f;
#pragma unroll 4
    for (int r = 0; r < 128; r++) {
        float e = __expf(p[r * DIM] - m);
        p[r * DIM] = e;
        s += e;
    }
    psum[chunk * DIM + c] = s;
}
__global__ void kcolsum_reduce(const float* __restrict__ psum, float* __restrict__ colinv) {
    int c = threadIdx.x;
    float s = 0.0f;
#pragma unroll 8
    for (int i = 0; i < 64; i++) s += psum[i * DIM + c];
    colinv[c] = 1.0f / s;
}

__global__ void ctx_zero_kernel(float* __restrict__ ctx) {
    ctx[blockIdx.x * 256 + threadIdx.x] = 0.0f;
}
__global__ void __launch_bounds__(256)
ctx_kernel(const float* __restrict__ E, const float* __restrict__ V, float* __restrict__ ctx) {
    int h = blockIdx.x, chunk = blockIdx.y;
    __shared__ float Es[32][64];
    __shared__ float Vs[32][64];
    int tid = threadIdx.x;
    int tx = tid & 15, ty = tid >> 4;
    float acc[4][4] = {};
    int rbase = chunk * 512;
    for (int r0 = 0; r0 < 512; r0 += 32) {
#pragma unroll
        for (int ld = 0; ld < 2; ld++) {
            int ii = tid + ld * 256;
            int rr = ii >> 4, c4 = (ii & 15) * 4;
            *(float4*)&Es[rr][c4] = *(const float4*)(E + (rbase + r0 + rr) * DIM + h * DH + c4);
            *(float4*)&Vs[rr][c4] = *(const float4*)(V + (rbase + r0 + rr) * DIM + h * DH + c4);
        }
        __syncthreads();
#pragma unroll
        for (int r = 0; r < 32; r++) {
            float4 a4 = *(float4*)&Es[r][ty * 4];
            float4 b4 = *(float4*)&Vs[r][tx * 4];
            float a[4] = {a4.x, a4.y, a4.z, a4.w};
            float b[4] = {b4.x, b4.y, b4.z, b4.w};
#pragma unroll
            for (int i = 0; i < 4; i++)
#pragma unroll
                for (int j = 0; j < 4; j++) acc[i][j] += a[i] * b[j];
        }
        __syncthreads();
    }
#pragma unroll
    for (int i = 0; i < 4; i++)
#pragma unroll
        for (int j = 0; j < 4; j++)
            atomicAdd(&ctx[h * (DH * DH) + (ty * 4 + i) * DH + tx * 4 + j], acc[i][j]);
}
__global__ void ctx_fix_kernel(float* __restrict__ ctx, const float* __restrict__ colinv) {
    int i = blockIdx.x * 256 + threadIdx.x;
    int h = i >> 12, d = (i >> 6) & 63;
    ctx[i] *= colinv[h * DH + d];
}

__global__ void __launch_bounds__(256)
attn_o_kernel(const float* __restrict__ Q, const float* __restrict__ ctx,
              __half* __restrict__ Ohi, __half* __restrict__ Olo) {
    int nt = blockIdx.x, h = blockIdx.y;
    __shared__ float Cs[64][64];
    __shared__ float Qs[64][64];
    int tid = threadIdx.x;
#pragma unroll
    for (int ld = 0; ld < 4; ld++) {
        int ii = tid + ld * 256;
        int rr = ii >> 4, c4 = (ii & 15) * 4;
        *(float4*)&Cs[rr][c4] = *(const float4*)(ctx + h * (DH * DH) + rr * DH + c4);
        *(float4*)&Qs[rr][c4] = *(const float4*)(Q + (nt * 64 + rr) * DIM + h * DH + c4);
    }
    __syncthreads();
    int tx = tid & 15, ty = tid >> 4;
    float acc[4][4] = {};
#pragma unroll 8
    for (int d = 0; d < 64; d++) {
        float a[4];
#pragma unroll
        for (int i = 0; i < 4; i++) a[i] = Qs[ty * 4 + i][d];
        float4 b4 = *(float4*)&Cs[d][tx * 4];
        float b[4] = {b4.x, b4.y, b4.z, b4.w};
#pragma unroll
        for (int i = 0; i < 4; i++)
#pragma unroll
            for (int j = 0; j < 4; j++) acc[i][j] += a[i] * b[j];
    }
#pragma unroll
    for (int i = 0; i < 4; i++) {
        __half h0, l0, h1, l1, h2, l2, h3, l3;
        hsplit(acc[i][0], h0, l0); hsplit(acc[i][1], h1, l1);
        hsplit(acc[i][2], h2, l2); hsplit(acc[i][3], h3, l3);
        __half2 ph[2] = {__halves2half2(h0, h1), __halves2half2(h2, h3)};
        __half2 pl[2] = {__halves2half2(l0, l1), __halves2half2(l2, l3)};
        int idx = (nt * 64 + ty * 4 + i) * DIM + h * DH + tx * 4;
        *(uint2*)&Ohi[idx] = *(uint2*)ph;
        *(uint2*)&Olo[idx] = *(uint2*)pl;
    }
}

// ================= host orchestration =================
extern "C" void kernel_launch(void* const* d_in, const int* in_sizes, int n_in,
                              void* d_out, int out_size) {
    const float* x     = (const float*)d_in[0];
    const float* ln1_g = (const float*)d_in[1];
    const float* ln1_b = (const float*)d_in[2];
    const float* Wq    = (const float*)d_in[3];
    const float* Wk    = (const float*)d_in[4];
    const float* Wv    = (const float*)d_in[5];
    const float* Wo    = (const float*)d_in[6];
    const float* bo    = (const float*)d_in[7];
    const float* ln2_g = (const float*)d_in[8];
    const float* ln2_b = (const float*)d_in[9];
    const float* W1    = (const float*)d_in[10];
    const float* b1    = (const float*)d_in[11];
    const float* W2    = (const float*)d_in[12];
    const float* b2    = (const float*)d_in[13];
    const float* projW = (const float*)d_in[14];
    const float* projb = (const float*)d_in[15];
    float* out = (float*)d_out;

    float *X, *Q, *K, *V, *pbuf, *colmax, *colinv, *ctx;
    __half *Hhi, *Hlo, *Ghi, *Glo, *Whi, *Wlo;
    cudaGetSymbolAddress((void**)&X, g_X);
    cudaGetSymbolAddress((void**)&Q, g_Q);
    cudaGetSymbolAddress((void**)&K, g_K);
    cudaGetSymbolAddress((void**)&V, g_V);
    cudaGetSymbolAddress((void**)&Hhi, g_Hhi);
    cudaGetSymbolAddress((void**)&Hlo, g_Hlo);
    cudaGetSymbolAddress((void**)&Ghi, g_Ghi);
    cudaGetSymbolAddress((void**)&Glo, g_Glo);
    cudaGetSymbolAddress((void**)&Whi, g_Whi);
    cudaGetSymbolAddress((void**)&Wlo, g_Wlo);
    cudaGetSymbolAddress((void**)&pbuf, g_pbuf);
    cudaGetSymbolAddress((void**)&colmax, g_colmax);
    cudaGetSymbolAddress((void**)&colinv, g_colinv);
    cudaGetSymbolAddress((void**)&ctx, g_ctx);

    cudaFuncSetAttribute(hgemm<0>, cudaFuncAttributeMaxDynamicSharedMemorySize, GEMM_SMEM);
    cudaFuncSetAttribute(hgemm<1>, cudaFuncAttributeMaxDynamicSharedMemorySize, GEMM_SMEM);
    cudaFuncSetAttribute(hgemm<2>, cudaFuncAttributeMaxDynamicSharedMemorySize, GEMM_SMEM);
    cudaFuncSetAttribute(hgemm<3>, cudaFuncAttributeMaxDynamicSharedMemorySize, GEMM_SMEM);

    pe_kernel<<<NSEQ * DIM / 256, 256>>>(x, X);
    wsplit_kernel<<<8192, 256>>>(Wq, Wk, Wv, Wo, W1, W2, projW, Whi, Wlo);

    dim3 gDD(4, 64), gFF(16, 64), gLL(32, 64);
    dim3 gctx(HEADS, 16), go(NSEQ / 64, HEADS);

    for (int l = 0; l < 2; l++) {
        ln_kernel<<<NSEQ, 128>>>(X, ln1_g + l * DIM, ln1_b + l * DIM, Hhi, Hlo);
        hgemm<0><<<gDD, 256, GEMM_SMEM>>>(Hhi, Hlo, Whi + WOFF_QKVO(l, 0), Wlo + WOFF_QKVO(l, 0),
                                          Q, nullptr, nullptr, nullptr, nullptr, 512, 512);
        hgemm<0><<<gDD, 256, GEMM_SMEM>>>(Hhi, Hlo, Whi + WOFF_QKVO(l, 1), Wlo + WOFF_QKVO(l, 1),
                                          K, nullptr, nullptr, nullptr, nullptr, 512, 512);
        hgemm<0><<<gDD, 256, GEMM_SMEM>>>(Hhi, Hlo, Whi + WOFF_QKVO(l, 2), Wlo + WOFF_QKVO(l, 2),
                                          V, nullptr, nullptr, nullptr, nullptr, 512, 512);

        qsoftmax_kernel<<<NSEQ, 256>>>(Q);
        kcolmax_kernel<<<64, 512>>>(K, pbuf);
        kcolmax_reduce<<<1, 512>>>(pbuf, colmax);
        kexp_kernel<<<64, 512>>>(K, colmax, pbuf);
        kcolsum_reduce<<<1, 512>>>(pbuf, colinv);
        ctx_zero_kernel<<<HEADS * DH * DH / 256, 256>>>(ctx);
        ctx_kernel<<<gctx, 256>>>(K, V, ctx);
        ctx_fix_kernel<<<HEADS * DH * DH / 256, 256>>>(ctx, colinv);
        attn_o_kernel<<<go, 256>>>(Q, ctx, Hhi, Hlo);

        hgemm<2><<<gDD, 256, GEMM_SMEM>>>(Hhi, Hlo, Whi + WOFF_QKVO(l, 3), Wlo + WOFF_QKVO(l, 3),
                                          X, nullptr, nullptr, bo + l * DIM, X, 512, 512);

        ln_kernel<<<NSEQ, 128>>>(X, ln2_g + l * DIM, ln2_b + l * DIM, Hhi, Hlo);
        hgemm<3><<<gFF, 256, GEMM_SMEM>>>(Hhi, Hlo, Whi + WOFF_W1(l), Wlo + WOFF_W1(l),
                                          nullptr, Ghi, Glo, b1 + l * FFD, nullptr, 512, 2048);
        hgemm<2><<<gDD, 256, GEMM_SMEM>>>(Ghi, Glo, Whi + WOFF_W2(l), Wlo + WOFF_W2(l),
                                          X, nullptr, nullptr, b2 + l * DIM, X, 2048, 512);
    }

    split_kernel<<<NSEQ * DIM / 1024, 256>>>(X, Hhi, Hlo);
    hgemm<1><<<gLL, 256, GEMM_SMEM>>>(Hhi, Hlo, Whi + WOFF_PJ, Wlo + WOFF_PJ,
                                      out, nullptr, nullptr, projb, nullptr, 512, 4096);
}

// round 10
// speedup vs baseline: 2.3012x; 1.1087x over previous
#include <cuda_runtime.h>
#include <cuda_fp16.h>
#include <math.h>
#include <stdint.h>

#define NSEQ 8192
#define DIM 512
#define HEADS 8
#define DH 64
#define FFD 2048
#define LLMD 4096
#define QKVS 1536                       // fused QKV row stride

#define PADK 40                         // halves per smem row (32 data + 8 pad)
#define ARRB (128 * PADK * 2)           // bytes per array per stage = 10240
#define STGB (4 * ARRB)                 // bytes per stage = 40960
#define GEMM_SMEM (2 * STGB)            // 81920 -> 2 CTAs/SM

__device__ __forceinline__ uint32_t smem_to_u32(const void* p) {
    uint32_t a;
    asm("{ .reg .u64 t; cvta.to.shared.u64 t, %1; cvt.u32.u64 %0, t; }" : "=r"(a) : "l"(p));
    return a;
}
#define CP_ASYNC16(sp, gp) \
    asm volatile("cp.async.cg.shared.global [%0], [%1], 16;" :: "r"(sp), "l"(gp))
#define CP_COMMIT() asm volatile("cp.async.commit_group;" ::: "memory")
#define CP_WAIT1()  asm volatile("cp.async.wait_group 1;" ::: "memory")
#define LDSM4(r0, r1, r2, r3, a) \
    asm volatile("ldmatrix.sync.aligned.m8n8.x4.shared.b16 {%0,%1,%2,%3}, [%4];" \
        : "=r"(r0), "=r"(r1), "=r"(r2), "=r"(r3) : "r"(a))
#define MMA16816(c0, c1, c2, c3, a0, a1, a2, a3, b0, b1) \
    asm volatile("mma.sync.aligned.m16n8k16.row.col.f32.f16.f16.f32 " \
        "{%0,%1,%2,%3},{%4,%5,%6,%7},{%8,%9},{%0,%1,%2,%3};" \
        : "+f"(c0), "+f"(c1), "+f"(c2), "+f"(c3) \
        : "r"(a0), "r"(a1), "r"(a2), "r"(a3), "r"(b0), "r"(b1))

__device__ __forceinline__ void hsplit(float v, __half& hi, __half& lo) {
    hi = __float2half_rn(v);
    lo = __float2half_rn(v - __half2float(hi));
}
__device__ __forceinline__ float gelu_exact(float v) {
    return 0.5f * v * (1.0f + erff(v * 0.70710678118654752f));
}

// ================= static scratch =================
__device__ float g_X[NSEQ * DIM];
__device__ float g_QKV[NSEQ * QKVS];
__device__ __half g_Hhi[NSEQ * DIM];
__device__ __half g_Hlo[NSEQ * DIM];
__device__ __half g_Ghi[NSEQ * FFD];
__device__ __half g_Glo[NSEQ * FFD];
#define WTOT 8388608
__device__ __half g_Whi[WTOT];
__device__ __half g_Wlo[WTOT];
__device__ float g_pbuf[64 * DIM];
__device__ float g_colmax[DIM];
__device__ float g_colinv[DIM];
__device__ float g_ctx[HEADS * DH * DH];

#define WOFF_QKVO(l, j) ((size_t)((l) * 4 + (j)) * 262144)
#define WOFF_W1(l) (2097152 + (size_t)(l) * 1048576)
#define WOFF_W2(l) (4194304 + (size_t)(l) * 1048576)
#define WOFF_PJ 6291456

// ================= weight transpose + fp16 split =================
__global__ void wsplit_kernel(const float* __restrict__ Wq, const float* __restrict__ Wk,
                              const float* __restrict__ Wv, const float* __restrict__ Wo,
                              const float* __restrict__ W1, const float* __restrict__ W2,
                              const float* __restrict__ Pj,
                              __half* __restrict__ Whi, __half* __restrict__ Wlo) {
    __shared__ float s[32][33];
    int b = blockIdx.x;
    const float* src;
    size_t dst;
    int K, N, tile;
    if (b < 2048) {
        int m = b >> 8, l = m >> 2, j = m & 3;
        tile = b & 255;
        const float* ptrs[4] = {Wq, Wk, Wv, Wo};
        src = ptrs[j] + (size_t)l * 262144;
        K = 512; N = 512; dst = (size_t)m * 262144;
    } else if (b < 4096) {
        int i = b - 2048, l = i >> 10;
        tile = i & 1023;
        src = W1 + (size_t)l * 1048576;
        K = 512; N = 2048; dst = WOFF_W1(l);
    } else if (b < 6144) {
        int i = b - 4096, l = i >> 10;
        tile = i & 1023;
        src = W2 + (size_t)l * 1048576;
        K = 2048; N = 512; dst = WOFF_W2(l);
    } else {
        tile = b - 6144;
        src = Pj;
        K = 512; N = 4096; dst = WOFF_PJ;
    }
    int tpr = N >> 5;
    int n0 = (tile % tpr) * 32, k0 = (tile / tpr) * 32;
    int c = threadIdx.x & 31, r0 = threadIdx.x >> 5;
#pragma unroll
    for (int i = 0; i < 4; i++) {
        int r = r0 + i * 8;
        s[r][c] = src[(size_t)(k0 + r) * N + n0 + c];
    }
    __syncthreads();
#pragma unroll
    for (int i = 0; i < 4; i++) {
        int r = r0 + i * 8;
        __half hi, lo;
        hsplit(s[c][r], hi, lo);
        size_t o = dst + (size_t)(n0 + r) * K + k0 + c;
        Whi[o] = hi;
        Wlo[o] = lo;
    }
}

// ================= HMMA GEMM: C[M,N] = A[M,K] * B[N,K]^T, fp16x2 split =================
// 2-stage cp.async pipeline, 2 CTAs/SM.
// EPI: 0 fp32, 1 +bias fp32, 2 +bias+residual fp32, 3 +bias+GELU -> fp16 hi/lo
template <int EPI>
__global__ void __launch_bounds__(256, 2)
hgemm(const __half* __restrict__ Ahg, const __half* __restrict__ Alg,
      const __half* __restrict__ Bhg, const __half* __restrict__ Blg,
      float* __restrict__ C, __half* __restrict__ Chi, __half* __restrict__ Clo,
      const float* __restrict__ bias, const float* __restrict__ R, int Ktot, int N) {
    extern __shared__ char smem[];
    const int tid = threadIdx.x, lane = tid & 31, wid = tid >> 5;
    const int warpM = (wid & 1) * 64, warpN = (wid >> 1) * 32;
    const int rBase = blockIdx.y * 128, cBase = blockIdx.x * 128;
    const int nch = Ktot >> 5;
    const uint32_t sbase = smem_to_u32(smem);

    const int ldrow = tid >> 2, ldch = tid & 3;

    auto issue_load = [&](int chunk, int stg) {
        uint32_t sb = sbase + stg * STGB;
        int k0 = chunk * 32;
#pragma unroll
        for (int i = 0; i < 8; i++) {
            const int arr = i >> 1;
            int row = ((i & 1) << 6) + ldrow;
            const __half* gp;
            if (arr == 0)      gp = Ahg + (size_t)(rBase + row) * Ktot;
            else if (arr == 1) gp = Alg + (size_t)(rBase + row) * Ktot;
            else if (arr == 2) gp = Bhg + (size_t)(cBase + row) * Ktot;
            else               gp = Blg + (size_t)(cBase + row) * Ktot;
            gp += k0 + ldch * 8;
            uint32_t sp = sb + arr * ARRB + (uint32_t)((row * PADK + ldch * 8) * 2);
            CP_ASYNC16(sp, gp);
        }
        CP_COMMIT();
    };

    // ldmatrix lane offsets: canonical &T[lane%16][(lane/16)*8]
    const int rr = lane & 7, tt = (lane >> 3) & 1, kp = (lane >> 4) * 8;
    uint32_t offA[4], offB[2];
#pragma unroll
    for (int mt = 0; mt < 4; mt++)
        offA[mt] = (uint32_t)(((warpM + mt * 16 + tt * 8 + rr) * PADK + kp) * 2);
#pragma unroll
    for (int p = 0; p < 2; p++)
        offB[p] = (uint32_t)(((warpN + p * 16 + tt * 8 + rr) * PADK + kp) * 2);

    float acc[4][4][4];
#pragma unroll
    for (int mt = 0; mt < 4; mt++)
#pragma unroll
        for (int nt = 0; nt < 4; nt++)
#pragma unroll
            for (int u = 0; u < 4; u++) acc[mt][nt][u] = 0.0f;

    issue_load(0, 0);
    issue_load(1, 1);

    for (int c = 0; c < nch; c++) {
        CP_WAIT1();
        __syncthreads();
        uint32_t sb = sbase + (c & 1) * STGB;
#pragma unroll
        for (int ks = 0; ks < 2; ks++) {
            uint32_t ah[4][4], al[4][4], bh[2][4], bl[2][4];
#pragma unroll
            for (int mt = 0; mt < 4; mt++)
                LDSM4(ah[mt][0], ah[mt][1], ah[mt][2], ah[mt][3], sb + offA[mt] + ks * 32);
#pragma unroll
            for (int p = 0; p < 2; p++)
                LDSM4(bh[p][0], bh[p][1], bh[p][2], bh[p][3], sb + 2 * ARRB + offB[p] + ks * 32);
#pragma unroll
            for (int mt = 0; mt < 4; mt++)
#pragma unroll
                for (int nt = 0; nt < 4; nt++)
                    MMA16816(acc[mt][nt][0], acc[mt][nt][1], acc[mt][nt][2], acc[mt][nt][3],
                             ah[mt][0], ah[mt][1], ah[mt][2], ah[mt][3],
                             bh[nt >> 1][nt & 1], bh[nt >> 1][2 + (nt & 1)]);
#pragma unroll
            for (int p = 0; p < 2; p++)
                LDSM4(bl[p][0], bl[p][1], bl[p][2], bl[p][3], sb + 3 * ARRB + offB[p] + ks * 32);
#pragma unroll
            for (int mt = 0; mt < 4; mt++)
#pragma unroll
                for (int nt = 0; nt < 4; nt++)
                    MMA16816(acc[mt][nt][0], acc[mt][nt][1], acc[mt][nt][2], acc[mt][nt][3],
                             ah[mt][0], ah[mt][1], ah[mt][2], ah[mt][3],
                             bl[nt >> 1][nt & 1], bl[nt >> 1][2 + (nt & 1)]);
#pragma unroll
            for (int mt = 0; mt < 4; mt++)
                LDSM4(al[mt][0], al[mt][1], al[mt][2], al[mt][3], sb + ARRB + offA[mt] + ks * 32);
#pragma unroll
            for (int mt = 0; mt < 4; mt++)
#pragma unroll
                for (int nt = 0; nt < 4; nt++)
                    MMA16816(acc[mt][nt][0], acc[mt][nt][1], acc[mt][nt][2], acc[mt][nt][3],
                             al[mt][0], al[mt][1], al[mt][2], al[mt][3],
                             bh[nt >> 1][nt & 1], bh[nt >> 1][2 + (nt & 1)]);
        }
        __syncthreads();   // all reads of stage (c&1) done before refilling it
        if (c + 2 < nch) issue_load(c + 2, c & 1);
        else CP_COMMIT();  // keep group-count invariant for CP_WAIT1
    }

    // epilogue
#pragma unroll
    for (int mt = 0; mt < 4; mt++) {
#pragma unroll
        for (int nt = 0; nt < 4; nt++) {
            int row = rBase + warpM + mt * 16 + (lane >> 2);
            int col = cBase + warpN + nt * 8 + (lane & 3) * 2;
#pragma unroll
            for (int h = 0; h < 2; h++) {
                int r = row + h * 8;
                float v0 = acc[mt][nt][h * 2 + 0];
                float v1 = acc[mt][nt][h * 2 + 1];
                if (EPI >= 1) { v0 += bias[col]; v1 += bias[col + 1]; }
                if (EPI == 2) {
                    v0 += R[(size_t)r * N + col];
                    v1 += R[(size_t)r * N + col + 1];
                }
                if (EPI == 3) {
                    v0 = gelu_exact(v0);
                    v1 = gelu_exact(v1);
                    __half h0, l0, h1, l1;
                    hsplit(v0, h0, l0);
                    hsplit(v1, h1, l1);
                    *(__half2*)&Chi[(size_t)r * N + col] = __halves2half2(h0, h1);
                    *(__half2*)&Clo[(size_t)r * N + col] = __halves2half2(l0, l1);
                } else {
                    float2 f2 = make_float2(v0, v1);
                    *(float2*)&C[(size_t)r * N + col] = f2;
                }
            }
        }
    }
}

// ================= elementwise / attention =================
__global__ void pe_kernel(const float* __restrict__ x, float* __restrict__ X) {
    int i = blockIdx.x * 256 + threadIdx.x;
    int n = i >> 9, d = i & 511, e = d & ~1;
    float divv = expf((float)e * (-9.210340371976184f / 512.0f));
    float ang = (float)n * divv;
    float pe = (d & 1) ? cosf(ang) : sinf(ang);
    X[i] = x[i] + pe;
}

__global__ void ln_kernel(const float* __restrict__ X, const float* __restrict__ g,
                          const float* __restrict__ b,
                          __half* __restrict__ Hhi, __half* __restrict__ Hlo) {
    int row = blockIdx.x;
    int t = threadIdx.x;
    float4 v = ((const float4*)(X + row * DIM))[t];
    float s = v.x + v.y + v.z + v.w;
    float s2 = v.x * v.x + v.y * v.y + v.z * v.z + v.w * v.w;
#pragma unroll
    for (int o = 16; o; o >>= 1) {
        s += __shfl_xor_sync(0xffffffffu, s, o);
        s2 += __shfl_xor_sync(0xffffffffu, s2, o);
    }
    __shared__ float ss[4], ss2[4];
    if ((t & 31) == 0) { ss[t >> 5] = s; ss2[t >> 5] = s2; }
    __syncthreads();
    s = ss[0] + ss[1] + ss[2] + ss[3];
    s2 = ss2[0] + ss2[1] + ss2[2] + ss2[3];
    float mu = s * (1.0f / DIM);
    float var = s2 * (1.0f / DIM) - mu * mu;
    float rstd = rsqrtf(var + 1e-5f);
    float4 gg = ((const float4*)g)[t];
    float4 bb = ((const float4*)b)[t];
    float o0 = (v.x - mu) * rstd * gg.x + bb.x;
    float o1 = (v.y - mu) * rstd * gg.y + bb.y;
    float o2 = (v.z - mu) * rstd * gg.z + bb.z;
    float o3 = (v.w - mu) * rstd * gg.w + bb.w;
    __half h0, l0, h1, l1, h2, l2, h3, l3;
    hsplit(o0, h0, l0); hsplit(o1, h1, l1); hsplit(o2, h2, l2); hsplit(o3, h3, l3);
    __half2 ph[2] = {__halves2half2(h0, h1), __halves2half2(h2, h3)};
    __half2 pl[2] = {__halves2half2(l0, l1), __halves2half2(l2, l3)};
    *(uint2*)&Hhi[row * DIM + t * 4] = *(uint2*)ph;
    *(uint2*)&Hlo[row * DIM + t * 4] = *(uint2*)pl;
}

__global__ void split_kernel(const float* __restrict__ X,
                             __half* __restrict__ Hhi, __half* __restrict__ Hlo) {
    int i = blockIdx.x * 256 + threadIdx.x;
    float4 v = ((const float4*)X)[i];
    __half h0, l0, h1, l1, h2, l2, h3, l3;
    hsplit(v.x, h0, l0); hsplit(v.y, h1, l1); hsplit(v.z, h2, l2); hsplit(v.w, h3, l3);
    __half2 ph[2] = {__halves2half2(h0, h1), __halves2half2(h2, h3)};
    __half2 pl[2] = {__halves2half2(l0, l1), __halves2half2(l2, l3)};
    *(uint2*)&Hhi[i * 4] = *(uint2*)ph;
    *(uint2*)&Hlo[i * 4] = *(uint2*)pl;
}

// q softmax in fused QKV buffer (row stride QKVS)
__global__ void qsoftmax_kernel(float* __restrict__ QKV) {
    int row = blockIdx.x;
    int wid = threadIdx.x >> 5, lane = threadIdx.x & 31;
    float2* p = (float2*)(QKV + (size_t)row * QKVS + wid * DH) + lane;
    float2 v = *p;
    float m = fmaxf(v.x, v.y);
#pragma unroll
    for (int o = 16; o; o >>= 1) m = fmaxf(m, __shfl_xor_sync(0xffffffffu, m, o));
    float e0 = __expf(v.x - m), e1 = __expf(v.y - m);
    float s = e0 + e1;
#pragma unroll
    for (int o = 16; o; o >>= 1) s += __shfl_xor_sync(0xffffffffu, s, o);
    float inv = 0.125f / s;
    v.x = e0 * inv;
    v.y = e1 * inv;
    *p = v;
}

// K column stats on fused buffer (Kb = QKV + 512, stride QKVS)
__global__ void kcolmax_kernel(const float* __restrict__ Kb, float* __restrict__ pmax) {
    int c = threadIdx.x, chunk = blockIdx.x;
    const float* p = Kb + (size_t)chunk * 128 * QKVS + c;
    float m = -1e30f;
#pragma unroll 4
    for (int r = 0; r < 128; r++) m = fmaxf(m, p[(size_t)r * QKVS]);
    pmax[chunk * DIM + c] = m;
}
__global__ void kcolmax_reduce(const float* __restrict__ pmax, float* __restrict__ colmax) {
    int c = threadIdx.x;
    float m = -1e30f;
#pragma unroll 8
    for (int i = 0; i < 64; i++) m = fmaxf(m, pmax[i * DIM + c]);
    colmax[c] = m;
}
__global__ void kexp_kernel(float* __restrict__ Kb, const float* __restrict__ colmax,
                            float* __restrict__ psum) {
    int c = threadIdx.x, chunk = blockIdx.x;
    float m = colmax[c];
    float* p = Kb + (size_t)chunk * 128 * QKVS + c;
    float s = 0.0f;
#pragma unroll 4
    for (int r = 0; r < 128; r++) {
        float e = __expf(p[(size_t)r * QKVS] - m);
        p[(size_t)r * QKVS] = e;
        s += e;
    }
    psum[chunk * DIM + c] = s;
}
__global__ void kcolsum_reduce(const float* __restrict__ psum, float* __restrict__ colinv) {
    int c = threadIdx.x;
    float s = 0.0f;
#pragma unroll 8
    for (int i = 0; i < 64; i++) s += psum[i * DIM + c];
    colinv[c] = 1.0f / s;
}

__global__ void ctx_zero_kernel(float* __restrict__ ctx) {
    ctx[blockIdx.x * 256 + threadIdx.x] = 0.0f;
}
// ctx = E^T V, E = QKV+512, V = QKV+1024, stride QKVS
__global__ void __launch_bounds__(256)
ctx_kernel(const float* __restrict__ E, const float* __restrict__ V, float* __restrict__ ctx) {
    int h = blockIdx.x, chunk = blockIdx.y;
    __shared__ float Es[32][64];
    __shared__ float Vs[32][64];
    int tid = threadIdx.x;
    int tx = tid & 15, ty = tid >> 4;
    float acc[4][4] = {};
    int rbase = chunk * 512;
    for (int r0 = 0; r0 < 512; r0 += 32) {
#pragma unroll
        for (int ld = 0; ld < 2; ld++) {
            int ii = tid + ld * 256;
            int rr = ii >> 4, c4 = (ii & 15) * 4;
            size_t base = (size_t)(rbase + r0 + rr) * QKVS + h * DH + c4;
            *(float4*)&Es[rr][c4] = *(const float4*)(E + base);
            *(float4*)&Vs[rr][c4] = *(const float4*)(V + base);
        }
        __syncthreads();
#pragma unroll
        for (int r = 0; r < 32; r++) {
            float4 a4 = *(float4*)&Es[r][ty * 4];
            float4 b4 = *(float4*)&Vs[r][tx * 4];
            float a[4] = {a4.x, a4.y, a4.z, a4.w};
            float b[4] = {b4.x, b4.y, b4.z, b4.w};
#pragma unroll
            for (int i = 0; i < 4; i++)
#pragma unroll
                for (int j = 0; j < 4; j++) acc[i][j] += a[i] * b[j];
        }
        __syncthreads();
    }
#pragma unroll
    for (int i = 0; i < 4; i++)
#pragma unroll
        for (int j = 0; j < 4; j++)
            atomicAdd(&ctx[h * (DH * DH) + (ty * 4 + i) * DH + tx * 4 + j], acc[i][j]);
}
__global__ void ctx_fix_kernel(float* __restrict__ ctx, const float* __restrict__ colinv) {
    int i = blockIdx.x * 256 + threadIdx.x;
    int h = i >> 12, d = (i >> 6) & 63;
    ctx[i] *= colinv[h * DH + d];
}

// o = q_sm @ ctx ; Q in fused buffer (stride QKVS); writes fp16 hi/lo (stride DIM)
__global__ void __launch_bounds__(256)
attn_o_kernel(const float* __restrict__ Q, const float* __restrict__ ctx,
              __half* __restrict__ Ohi, __half* __restrict__ Olo) {
    int nt = blockIdx.x, h = blockIdx.y;
    __shared__ float Cs[64][64];
    __shared__ float Qs[64][64];
    int tid = threadIdx.x;
#pragma unroll
    for (int ld = 0; ld < 4; ld++) {
        int ii = tid + ld * 256;
        int rr = ii >> 4, c4 = (ii & 15) * 4;
        *(float4*)&Cs[rr][c4] = *(const float4*)(ctx + h * (DH * DH) + rr * DH + c4);
        *(float4*)&Qs[rr][c4] = *(const float4*)(Q + (size_t)(nt * 64 + rr) * QKVS + h * DH + c4);
    }
    __syncthreads();
    int tx = tid & 15, ty = tid >> 4;
    float acc[4][4] = {};
#pragma unroll 8
    for (int d = 0; d < 64; d++) {
        float a[4];
#pragma unroll
        for (int i = 0; i < 4; i++) a[i] = Qs[ty * 4 + i][d];
        float4 b4 = *(float4*)&Cs[d][tx * 4];
        float b[4] = {b4.x, b4.y, b4.z, b4.w};
#pragma unroll
        for (int i = 0; i < 4; i++)
#pragma unroll
            for (int j = 0; j < 4; j++) acc[i][j] += a[i] * b[j];
    }
#pragma unroll
    for (int i = 0; i < 4; i++) {
        __half h0, l0, h1, l1, h2, l2, h3, l3;
        hsplit(acc[i][0], h0, l0); hsplit(acc[i][1], h1, l1);
        hsplit(acc[i][2], h2, l2); hsplit(acc[i][3], h3, l3);
        __half2 ph[2] = {__halves2half2(h0, h1), __halves2half2(h2, h3)};
        __half2 pl[2] = {__halves2half2(l0, l1), __halves2half2(l2, l3)};
        int idx = (nt * 64 + ty * 4 + i) * DIM + h * DH + tx * 4;
        *(uint2*)&Ohi[idx] = *(uint2*)ph;
        *(uint2*)&Olo[idx] = *(uint2*)pl;
    }
}

// ================= host orchestration =================
extern "C" void kernel_launch(void* const* d_in, const int* in_sizes, int n_in,
                              void* d_out, int out_size) {
    const float* x     = (const float*)d_in[0];
    const float* ln1_g = (const float*)d_in[1];
    const float* ln1_b = (const float*)d_in[2];
    const float* Wq    = (const float*)d_in[3];
    const float* Wk    = (const float*)d_in[4];
    const float* Wv    = (const float*)d_in[5];
    const float* Wo    = (const float*)d_in[6];
    const float* bo    = (const float*)d_in[7];
    const float* ln2_g = (const float*)d_in[8];
    const float* ln2_b = (const float*)d_in[9];
    const float* W1    = (const float*)d_in[10];
    const float* b1    = (const float*)d_in[11];
    const float* W2    = (const float*)d_in[12];
    const float* b2    = (const float*)d_in[13];
    const float* projW = (const float*)d_in[14];
    const float* projb = (const float*)d_in[15];
    float* out = (float*)d_out;

    float *X, *QKV, *pbuf, *colmax, *colinv, *ctx;
    __half *Hhi, *Hlo, *Ghi, *Glo, *Whi, *Wlo;
    cudaGetSymbolAddress((void**)&X, g_X);
    cudaGetSymbolAddress((void**)&QKV, g_QKV);
    cudaGetSymbolAddress((void**)&Hhi, g_Hhi);
    cudaGetSymbolAddress((void**)&Hlo, g_Hlo);
    cudaGetSymbolAddress((void**)&Ghi, g_Ghi);
    cudaGetSymbolAddress((void**)&Glo, g_Glo);
    cudaGetSymbolAddress((void**)&Whi, g_Whi);
    cudaGetSymbolAddress((void**)&Wlo, g_Wlo);
    cudaGetSymbolAddress((void**)&pbuf, g_pbuf);
    cudaGetSymbolAddress((void**)&colmax, g_colmax);
    cudaGetSymbolAddress((void**)&colinv, g_colinv);
    cudaGetSymbolAddress((void**)&ctx, g_ctx);

    cudaFuncSetAttribute(hgemm<0>, cudaFuncAttributeMaxDynamicSharedMemorySize, GEMM_SMEM);
    cudaFuncSetAttribute(hgemm<1>, cudaFuncAttributeMaxDynamicSharedMemorySize, GEMM_SMEM);
    cudaFuncSetAttribute(hgemm<2>, cudaFuncAttributeMaxDynamicSharedMemorySize, GEMM_SMEM);
    cudaFuncSetAttribute(hgemm<3>, cudaFuncAttributeMaxDynamicSharedMemorySize, GEMM_SMEM);

    pe_kernel<<<NSEQ * DIM / 256, 256>>>(x, X);
    wsplit_kernel<<<8192, 256>>>(Wq, Wk, Wv, Wo, W1, W2, projW, Whi, Wlo);

    dim3 gQKV(12, 64), gDD(4, 64), gFF(16, 64), gLL(32, 64);
    dim3 gctx(HEADS, 16), go(NSEQ / 64, HEADS);

    for (int l = 0; l < 2; l++) {
        ln_kernel<<<NSEQ, 128>>>(X, ln1_g + l * DIM, ln1_b + l * DIM, Hhi, Hlo);
        // fused Q|K|V: weight rows for j=0,1,2 are contiguous in the table
        hgemm<0><<<gQKV, 256, GEMM_SMEM>>>(Hhi, Hlo, Whi + WOFF_QKVO(l, 0), Wlo + WOFF_QKVO(l, 0),
                                           QKV, nullptr, nullptr, nullptr, nullptr, 512, QKVS);

        qsoftmax_kernel<<<NSEQ, 256>>>(QKV);
        kcolmax_kernel<<<64, 512>>>(QKV + 512, pbuf);
        kcolmax_reduce<<<1, 512>>>(pbuf, colmax);
        kexp_kernel<<<64, 512>>>(QKV + 512, colmax, pbuf);
        kcolsum_reduce<<<1, 512>>>(pbuf, colinv);
        ctx_zero_kernel<<<HEADS * DH * DH / 256, 256>>>(ctx);
        ctx_kernel<<<gctx, 256>>>(QKV + 512, QKV + 1024, ctx);
        ctx_fix_kernel<<<HEADS * DH * DH / 256, 256>>>(ctx, colinv);
        attn_o_kernel<<<go, 256>>>(QKV, ctx, Hhi, Hlo);

        hgemm<2><<<gDD, 256, GEMM_SMEM>>>(Hhi, Hlo, Whi + WOFF_QKVO(l, 3), Wlo + WOFF_QKVO(l, 3),
                                          X, nullptr, nullptr, bo + l * DIM, X, 512, 512);

        ln_kernel<<<NSEQ, 128>>>(X, ln2_g + l * DIM, ln2_b + l * DIM, Hhi, Hlo);
        hgemm<3><<<gFF, 256, GEMM_SMEM>>>(Hhi, Hlo, Whi + WOFF_W1(l), Wlo + WOFF_W1(l),
                                          nullptr, Ghi, Glo, b1 + l * FFD, nullptr, 512, 2048);
        hgemm<2><<<gDD, 256, GEMM_SMEM>>>(Ghi, Glo, Whi + WOFF_W2(l), Wlo + WOFF_W2(l),
                                          X, nullptr, nullptr, b2 + l * DIM, X, 2048, 512);
    }

    split_kernel<<<NSEQ * DIM / 1024, 256>>>(X, Hhi, Hlo);
    hgemm<1><<<gLL, 256, GEMM_SMEM>>>(Hhi, Hlo, Whi + WOFF_PJ, Wlo + WOFF_PJ,
                                      out, nullptr, nullptr, projb, nullptr, 512, 4096);
}

// round 13
// speedup vs baseline: 2.6012x; 1.1303x over previous
#include <cuda_runtime.h>
#include <cuda_fp16.h>
#include <math.h>
#include <stdint.h>

#define NSEQ 8192
#define DIM 512
#define HEADS 8
#define DH 64
#define FFD 2048
#define LLMD 4096
#define QKVS 1536                       // fused QKV row stride

#define ARRB (128 * 64)                 // bytes per array per stage = 8192 (64B rows, XOR swizzle)
#define STGB (4 * ARRB)                 // bytes per stage = 32768
#define GEMM_SMEM (3 * STGB)            // 98304 -> 2 CTAs/SM (196KB/SM)

__device__ __forceinline__ uint32_t smem_to_u32(const void* p) {
    uint32_t a;
    asm("{ .reg .u64 t; cvta.to.shared.u64 t, %1; cvt.u32.u64 %0, t; }" : "=r"(a) : "l"(p));
    return a;
}
#define CP_ASYNC16(sp, gp) \
    asm volatile("cp.async.cg.shared.global [%0], [%1], 16;" :: "r"(sp), "l"(gp))
#define CP_COMMIT() asm volatile("cp.async.commit_group;" ::: "memory")
#define CP_WAIT1()  asm volatile("cp.async.wait_group 1;" ::: "memory")
#define LDSM4(r0, r1, r2, r3, a) \
    asm volatile("ldmatrix.sync.aligned.m8n8.x4.shared.b16 {%0,%1,%2,%3}, [%4];" \
        : "=r"(r0), "=r"(r1), "=r"(r2), "=r"(r3) : "r"(a))
#define MMA16816(c0, c1, c2, c3, a0, a1, a2, a3, b0, b1) \
    asm volatile("mma.sync.aligned.m16n8k16.row.col.f32.f16.f16.f32 " \
        "{%0,%1,%2,%3},{%4,%5,%6,%7},{%8,%9},{%0,%1,%2,%3};" \
        : "+f"(c0), "+f"(c1), "+f"(c2), "+f"(c3) \
        : "r"(a0), "r"(a1), "r"(a2), "r"(a3), "r"(b0), "r"(b1))

__device__ __forceinline__ void hsplit(float v, __half& hi, __half& lo) {
    hi = __float2half_rn(v);
    lo = __float2half_rn(v - __half2float(hi));
}
__device__ __forceinline__ float gelu_exact(float v) {
    return 0.5f * v * (1.0f + erff(v * 0.70710678118654752f));
}

// ================= static scratch =================
__device__ float g_X[NSEQ * DIM];
__device__ float g_QKV[NSEQ * QKVS];
__device__ __half g_Hhi[NSEQ * DIM];
__device__ __half g_Hlo[NSEQ * DIM];
__device__ __half g_Ghi[NSEQ * FFD];
__device__ __half g_Glo[NSEQ * FFD];
#define WTOT 8388608
__device__ __half g_Whi[WTOT];
__device__ __half g_Wlo[WTOT];
__device__ float g_pbuf[64 * DIM];
__device__ float g_colmax[DIM];
__device__ float g_colinv[DIM];
__device__ float g_ctx[HEADS * DH * DH];

#define WOFF_QKVO(l, j) ((size_t)((l) * 4 + (j)) * 262144)
#define WOFF_W1(l) (2097152 + (size_t)(l) * 1048576)
#define WOFF_W2(l) (4194304 + (size_t)(l) * 1048576)
#define WOFF_PJ 6291456

// ================= weight transpose + fp16 split =================
__global__ void wsplit_kernel(const float* __restrict__ Wq, const float* __restrict__ Wk,
                              const float* __restrict__ Wv, const float* __restrict__ Wo,
                              const float* __restrict__ W1, const float* __restrict__ W2,
                              const float* __restrict__ Pj,
                              __half* __restrict__ Whi, __half* __restrict__ Wlo) {
    __shared__ float s[32][33];
    int b = blockIdx.x;
    const float* src;
    size_t dst;
    int K, N, tile;
    if (b < 2048) {
        int m = b >> 8, l = m >> 2, j = m & 3;
        tile = b & 255;
        const float* ptrs[4] = {Wq, Wk, Wv, Wo};
        src = ptrs[j] + (size_t)l * 262144;
        K = 512; N = 512; dst = (size_t)m * 262144;
    } else if (b < 4096) {
        int i = b - 2048, l = i >> 10;
        tile = i & 1023;
        src = W1 + (size_t)l * 1048576;
        K = 512; N = 2048; dst = WOFF_W1(l);
    } else if (b < 6144) {
        int i = b - 4096, l = i >> 10;
        tile = i & 1023;
        src = W2 + (size_t)l * 1048576;
        K = 2048; N = 512; dst = WOFF_W2(l);
    } else {
        tile = b - 6144;
        src = Pj;
        K = 512; N = 4096; dst = WOFF_PJ;
    }
    int tpr = N >> 5;
    int n0 = (tile % tpr) * 32, k0 = (tile / tpr) * 32;
    int c = threadIdx.x & 31, r0 = threadIdx.x >> 5;
#pragma unroll
    for (int i = 0; i < 4; i++) {
        int r = r0 + i * 8;
        s[r][c] = src[(size_t)(k0 + r) * N + n0 + c];
    }
    __syncthreads();
#pragma unroll
    for (int i = 0; i < 4; i++) {
        int r = r0 + i * 8;
        __half hi, lo;
        hsplit(s[c][r], hi, lo);
        size_t o = dst + (size_t)(n0 + r) * K + k0 + c;
        Whi[o] = hi;
        Wlo[o] = lo;
    }
}

// ================= HMMA GEMM: C[M,N] = A[M,K] * B[N,K]^T, fp16x2 split =================
// 3-stage cp.async pipeline (XOR-swizzled 64B rows), 2 CTAs/SM, one barrier per chunk.
// EPI: 0 fp32, 1 +bias fp32, 2 +bias+residual fp32, 3 +bias+GELU -> fp16 hi/lo
template <int EPI>
__global__ void __launch_bounds__(256, 2)
hgemm(const __half* __restrict__ Ahg, const __half* __restrict__ Alg,
      const __half* __restrict__ Bhg, const __half* __restrict__ Blg,
      float* __restrict__ C, __half* __restrict__ Chi, __half* __restrict__ Clo,
      const float* __restrict__ bias, const float* __restrict__ R, int Ktot, int N) {
    extern __shared__ char smem[];
    const int tid = threadIdx.x, lane = tid & 31, wid = tid >> 5;
    const int warpM = (wid & 1) * 64, warpN = (wid >> 1) * 32;
    const int rBase = blockIdx.y * 128, cBase = blockIdx.x * 128;
    const int nch = Ktot >> 5;
    const uint32_t sbase = smem_to_u32(smem);

    const int ldrow = tid >> 2, ldc16 = tid & 3;

    auto issue_load = [&](int chunk, int stg) {
        uint32_t sb = sbase + stg * STGB;
        int k0 = chunk * 32;
#pragma unroll
        for (int i = 0; i < 8; i++) {
            const int arr = i >> 1;
            int row = ((i & 1) << 6) + ldrow;
            const __half* gp;
            if (arr == 0)      gp = Ahg + (size_t)(rBase + row) * Ktot;
            else if (arr == 1) gp = Alg + (size_t)(rBase + row) * Ktot;
            else if (arr == 2) gp = Bhg + (size_t)(cBase + row) * Ktot;
            else               gp = Blg + (size_t)(cBase + row) * Ktot;
            gp += k0 + ldc16 * 8;
            uint32_t sp = sb + arr * ARRB +
                          (uint32_t)(row * 64 + ((ldc16 ^ ((row >> 1) & 3)) << 4));
            CP_ASYNC16(sp, gp);
        }
        CP_COMMIT();
    };

    // ldmatrix lane mapping: lanes0-7 tile rows+0..7, 8-15 rows+8..15, 16-31 same rows k+8
    const int rr = lane & 7, tt = (lane >> 3) & 1, c16b = lane >> 4;  // c16b: k-half 16B index
    uint32_t abase[4], asz[4], bbase[2], bsz[2];
#pragma unroll
    for (int mt = 0; mt < 4; mt++) {
        int row = warpM + mt * 16 + tt * 8 + rr;
        abase[mt] = (uint32_t)(row * 64);
        asz[mt] = (uint32_t)((c16b ^ ((row >> 1) & 3)) << 4);
    }
#pragma unroll
    for (int p = 0; p < 2; p++) {
        int row = warpN + p * 16 + tt * 8 + rr;
        bbase[p] = (uint32_t)(row * 64);
        bsz[p] = (uint32_t)((c16b ^ ((row >> 1) & 3)) << 4);
    }

    float acc[4][4][4];
#pragma unroll
    for (int mt = 0; mt < 4; mt++)
#pragma unroll
        for (int nt = 0; nt < 4; nt++)
#pragma unroll
            for (int u = 0; u < 4; u++) acc[mt][nt][u] = 0.0f;

    issue_load(0, 0);
    issue_load(1, 1);

    for (int c = 0; c < nch; c++) {
        CP_WAIT1();
        __syncthreads();
        if (c + 2 < nch) issue_load(c + 2, (c + 2) % 3);  // stage (c+2)%3 == (c-1)%3: reads done
        else CP_COMMIT();                                  // keep group-count invariant
        uint32_t sb = sbase + (c % 3) * STGB;
#pragma unroll
        for (int ks = 0; ks < 2; ks++) {
            const uint32_t kx = (uint32_t)(ks << 5);   // (ks<<1)<<4 byte offset, XORed with swz
            uint32_t ah[4][4], al[4][4], bh[2][4], bl[2][4];
#pragma unroll
            for (int mt = 0; mt < 4; mt++)
                LDSM4(ah[mt][0], ah[mt][1], ah[mt][2], ah[mt][3],
                      sb + abase[mt] + (kx ^ asz[mt]));
#pragma unroll
            for (int p = 0; p < 2; p++)
                LDSM4(bh[p][0], bh[p][1], bh[p][2], bh[p][3],
                      sb + 2 * ARRB + bbase[p] + (kx ^ bsz[p]));
#pragma unroll
            for (int mt = 0; mt < 4; mt++)
#pragma unroll
                for (int nt = 0; nt < 4; nt++)
                    MMA16816(acc[mt][nt][0], acc[mt][nt][1], acc[mt][nt][2], acc[mt][nt][3],
                             ah[mt][0], ah[mt][1], ah[mt][2], ah[mt][3],
                             bh[nt >> 1][nt & 1], bh[nt >> 1][2 + (nt & 1)]);
#pragma unroll
            for (int p = 0; p < 2; p++)
                LDSM4(bl[p][0], bl[p][1], bl[p][2], bl[p][3],
                      sb + 3 * ARRB + bbase[p] + (kx ^ bsz[p]));
#pragma unroll
            for (int mt = 0; mt < 4; mt++)
#pragma unroll
                for (int nt = 0; nt < 4; nt++)
                    MMA16816(acc[mt][nt][0], acc[mt][nt][1], acc[mt][nt][2], acc[mt][nt][3],
                             ah[mt][0], ah[mt][1], ah[mt][2], ah[mt][3],
                             bl[nt >> 1][nt & 1], bl[nt >> 1][2 + (nt & 1)]);
#pragma unroll
            for (int mt = 0; mt < 4; mt++)
                LDSM4(al[mt][0], al[mt][1], al[mt][2], al[mt][3],
                      sb + ARRB + abase[mt] + (kx ^ asz[mt]));
#pragma unroll
            for (int mt = 0; mt < 4; mt++)
#pragma unroll
                for (int nt = 0; nt < 4; nt++)
                    MMA16816(acc[mt][nt][0], acc[mt][nt][1], acc[mt][nt][2], acc[mt][nt][3],
                             al[mt][0], al[mt][1], al[mt][2], al[mt][3],
                             bh[nt >> 1][nt & 1], bh[nt >> 1][2 + (nt & 1)]);
        }
    }

    // epilogue
#pragma unroll
    for (int mt = 0; mt < 4; mt++) {
#pragma unroll
        for (int nt = 0; nt < 4; nt++) {
            int row = rBase + warpM + mt * 16 + (lane >> 2);
            int col = cBase + warpN + nt * 8 + (lane & 3) * 2;
#pragma unroll
            for (int h = 0; h < 2; h++) {
                int r = row + h * 8;
                float v0 = acc[mt][nt][h * 2 + 0];
                float v1 = acc[mt][nt][h * 2 + 1];
                if (EPI >= 1) { v0 += bias[col]; v1 += bias[col + 1]; }
                if (EPI == 2) {
                    v0 += R[(size_t)r * N + col];
                    v1 += R[(size_t)r * N + col + 1];
                }
                if (EPI == 3) {
                    v0 = gelu_exact(v0);
                    v1 = gelu_exact(v1);
                    __half h0, l0, h1, l1;
                    hsplit(v0, h0, l0);
                    hsplit(v1, h1, l1);
                    *(__half2*)&Chi[(size_t)r * N + col] = __halves2half2(h0, h1);
                    *(__half2*)&Clo[(size_t)r * N + col] = __halves2half2(l0, l1);
                } else {
                    float2 f2 = make_float2(v0, v1);
                    *(float2*)&C[(size_t)r * N + col] = f2;
                }
            }
        }
    }
}

// ================= elementwise / attention =================
__global__ void pe_kernel(const float* __restrict__ x, float* __restrict__ X) {
    int i = blockIdx.x * 256 + threadIdx.x;
    int n = i >> 9, d = i & 511, e = d & ~1;
    float divv = expf((float)e * (-9.210340371976184f / 512.0f));
    float ang = (float)n * divv;
    float pe = (d & 1) ? cosf(ang) : sinf(ang);
    X[i] = x[i] + pe;
}

__global__ void ln_kernel(const float* __restrict__ X, const float* __restrict__ g,
                          const float* __restrict__ b,
                          __half* __restrict__ Hhi, __half* __restrict__ Hlo) {
    int row = blockIdx.x;
    int t = threadIdx.x;
    float4 v = ((const float4*)(X + row * DIM))[t];
    float s = v.x + v.y + v.z + v.w;
    float s2 = v.x * v.x + v.y * v.y + v.z * v.z + v.w * v.w;
#pragma unroll
    for (int o = 16; o; o >>= 1) {
        s += __shfl_xor_sync(0xffffffffu, s, o);
        s2 += __shfl_xor_sync(0xffffffffu, s2, o);
    }
    __shared__ float ss[4], ss2[4];
    if ((t & 31) == 0) { ss[t >> 5] = s; ss2[t >> 5] = s2; }
    __syncthreads();
    s = ss[0] + ss[1] + ss[2] + ss[3];
    s2 = ss2[0] + ss2[1] + ss2[2] + ss2[3];
    float mu = s * (1.0f / DIM);
    float var = s2 * (1.0f / DIM) - mu * mu;
    float rstd = rsqrtf(var + 1e-5f);
    float4 gg = ((const float4*)g)[t];
    float4 bb = ((const float4*)b)[t];
    float o0 = (v.x - mu) * rstd * gg.x + bb.x;
    float o1 = (v.y - mu) * rstd * gg.y + bb.y;
    float o2 = (v.z - mu) * rstd * gg.z + bb.z;
    float o3 = (v.w - mu) * rstd * gg.w + bb.w;
    __half h0, l0, h1, l1, h2, l2, h3, l3;
    hsplit(o0, h0, l0); hsplit(o1, h1, l1); hsplit(o2, h2, l2); hsplit(o3, h3, l3);
    __half2 ph[2] = {__halves2half2(h0, h1), __halves2half2(h2, h3)};
    __half2 pl[2] = {__halves2half2(l0, l1), __halves2half2(l2, l3)};
    *(uint2*)&Hhi[row * DIM + t * 4] = *(uint2*)ph;
    *(uint2*)&Hlo[row * DIM + t * 4] = *(uint2*)pl;
}

__global__ void split_kernel(const float* __restrict__ X,
                             __half* __restrict__ Hhi, __half* __restrict__ Hlo) {
    int i = blockIdx.x * 256 + threadIdx.x;
    float4 v = ((const float4*)X)[i];
    __half h0, l0, h1, l1, h2, l2, h3, l3;
    hsplit(v.x, h0, l0); hsplit(v.y, h1, l1); hsplit(v.z, h2, l2); hsplit(v.w, h3, l3);
    __half2 ph[2] = {__halves2half2(h0, h1), __halves2half2(h2, h3)};
    __half2 pl[2] = {__halves2half2(l0, l1), __halves2half2(l2, l3)};
    *(uint2*)&Hhi[i * 4] = *(uint2*)ph;
    *(uint2*)&Hlo[i * 4] = *(uint2*)pl;
}

// q softmax in fused QKV buffer (row stride QKVS)
__global__ void qsoftmax_kernel(float* __restrict__ QKV) {
    int row = blockIdx.x;
    int wid = threadIdx.x >> 5, lane = threadIdx.x & 31;
    float2* p = (float2*)(QKV + (size_t)row * QKVS + wid * DH) + lane;
    float2 v = *p;
    float m = fmaxf(v.x, v.y);
#pragma unroll
    for (int o = 16; o; o >>= 1) m = fmaxf(m, __shfl_xor_sync(0xffffffffu, m, o));
    float e0 = __expf(v.x - m), e1 = __expf(v.y - m);
    float s = e0 + e1;
#pragma unroll
    for (int o = 16; o; o >>= 1) s += __shfl_xor_sync(0xffffffffu, s, o);
    float inv = 0.125f / s;
    v.x = e0 * inv;
    v.y = e1 * inv;
    *p = v;
}

// K column stats on fused buffer (Kb = QKV + 512, stride QKVS)
__global__ void kcolmax_kernel(const float* __restrict__ Kb, float* __restrict__ pmax) {
    int c = threadIdx.x, chunk = blockIdx.x;
    const float* p = Kb + (size_t)chunk * 128 * QKVS + c;
    float m = -1e30f;
#pragma unroll 4
    for (int r = 0; r < 128; r++) m = fmaxf(m, p[(size_t)r * QKVS]);
    pmax[chunk * DIM + c] = m;
}
__global__ void kcolmax_reduce(const float* __restrict__ pmax, float* __restrict__ colmax) {
    int c = threadIdx.x;
    float m = -1e30f;
#pragma unroll 8
    for (int i = 0; i < 64; i++) m = fmaxf(m, pmax[i * DIM + c]);
    colmax[c] = m;
}
__global__ void kexp_kernel(float* __restrict__ Kb, const float* __restrict__ colmax,
                            float* __restrict__ psum) {
    int c = threadIdx.x, chunk = blockIdx.x;
    float m = colmax[c];
    float* p = Kb + (size_t)chunk * 128 * QKVS + c;
    float s = 0.0f;
#pragma unroll 4
    for (int r = 0; r < 128; r++) {
        float e = __expf(p[(size_t)r * QKVS] - m);
        p[(size_t)r * QKVS] = e;
        s += e;
    }
    psum[chunk * DIM + c] = s;
}
__global__ void kcolsum_reduce(const float* __restrict__ psum, float* __restrict__ colinv) {
    int c = threadIdx.x;
    float s = 0.0f;
#pragma unroll 8
    for (int i = 0; i < 64; i++) s += psum[i * DIM + c];
    colinv[c] = 1.0f / s;
}

__global__ void ctx_zero_kernel(float* __restrict__ ctx) {
    ctx[blockIdx.x * 256 + threadIdx.x] = 0.0f;
}
// ctx = E^T V, E = QKV+512, V = QKV+1024, stride QKVS
__global__ void __launch_bounds__(256)
ctx_kernel(const float* __restrict__ E, const float* __restrict__ V, float* __restrict__ ctx) {
    int h = blockIdx.x, chunk = blockIdx.y;
    __shared__ float Es[32][64];
    __shared__ float Vs[32][64];
    int tid = threadIdx.x;
    int tx = tid & 15, ty = tid >> 4;
    float acc[4][4] = {};
    int rbase = chunk * 512;
    for (int r0 = 0; r0 < 512; r0 += 32) {
#pragma unroll
        for (int ld = 0; ld < 2; ld++) {
            int ii = tid + ld * 256;
            int rr = ii >> 4, c4 = (ii & 15) * 4;
            size_t base = (size_t)(rbase + r0 + rr) * QKVS + h * DH + c4;
            *(float4*)&Es[rr][c4] = *(const float4*)(E + base);
            *(float4*)&Vs[rr][c4] = *(const float4*)(V + base);
        }
        __syncthreads();
#pragma unroll
        for (int r = 0; r < 32; r++) {
            float4 a4 = *(float4*)&Es[r][ty * 4];
            float4 b4 = *(float4*)&Vs[r][tx * 4];
            float a[4] = {a4.x, a4.y, a4.z, a4.w};
            float b[4] = {b4.x, b4.y, b4.z, b4.w};
#pragma unroll
            for (int i = 0; i < 4; i++)
#pragma unroll
                for (int j = 0; j < 4; j++) acc[i][j] += a[i] * b[j];
        }
        __syncthreads();
    }
#pragma unroll
    for (int i = 0; i < 4; i++)
#pragma unroll
        for (int j = 0; j < 4; j++)
            atomicAdd(&ctx[h * (DH * DH) + (ty * 4 + i) * DH + tx * 4 + j], acc[i][j]);
}
__global__ void ctx_fix_kernel(float* __restrict__ ctx, const float* __restrict__ colinv) {
    int i = blockIdx.x * 256 + threadIdx.x;
    int h = i >> 12, d = (i >> 6) & 63;
    ctx[i] *= colinv[h * DH + d];
}

// o = q_sm @ ctx ; Q in fused buffer (stride QKVS); writes fp16 hi/lo (stride DIM)
__global__ void __launch_bounds__(256)
attn_o_kernel(const float* __restrict__ Q, const float* __restrict__ ctx,
              __half* __restrict__ Ohi, __half* __restrict__ Olo) {
    int nt = blockIdx.x, h = blockIdx.y;
    __shared__ float Cs[64][64];
    __shared__ float Qs[64][64];
    int tid = threadIdx.x;
#pragma unroll
    for (int ld = 0; ld < 4; ld++) {
        int ii = tid + ld * 256;
        int rr = ii >> 4, c4 = (ii & 15) * 4;
        *(float4*)&Cs[rr][c4] = *(const float4*)(ctx + h * (DH * DH) + rr * DH + c4);
        *(float4*)&Qs[rr][c4] = *(const float4*)(Q + (size_t)(nt * 64 + rr) * QKVS + h * DH + c4);
    }
    __syncthreads();
    int tx = tid & 15, ty = tid >> 4;
    float acc[4][4] = {};
#pragma unroll 8
    for (int d = 0; d < 64; d++) {
        float a[4];
#pragma unroll
        for (int i = 0; i < 4; i++) a[i] = Qs[ty * 4 + i][d];
        float4 b4 = *(float4*)&Cs[d][tx * 4];
        float b[4] = {b4.x, b4.y, b4.z, b4.w};
#pragma unroll
        for (int i = 0; i < 4; i++)
#pragma unroll
            for (int j = 0; j < 4; j++) acc[i][j] += a[i] * b[j];
    }
#pragma unroll
    for (int i = 0; i < 4; i++) {
        __half h0, l0, h1, l1, h2, l2, h3, l3;
        hsplit(acc[i][0], h0, l0); hsplit(acc[i][1], h1, l1);
        hsplit(acc[i][2], h2, l2); hsplit(acc[i][3], h3, l3);
        __half2 ph[2] = {__halves2half2(h0, h1), __halves2half2(h2, h3)};
        __half2 pl[2] = {__halves2half2(l0, l1), __halves2half2(l2, l3)};
        int idx = (nt * 64 + ty * 4 + i) * DIM + h * DH + tx * 4;
        *(uint2*)&Ohi[idx] = *(uint2*)ph;
        *(uint2*)&Olo[idx] = *(uint2*)pl;
    }
}

// ================= host orchestration =================
extern "C" void kernel_launch(void* const* d_in, const int* in_sizes, int n_in,
                              void* d_out, int out_size) {
    const float* x     = (const float*)d_in[0];
    const float* ln1_g = (const float*)d_in[1];
    const float* ln1_b = (const float*)d_in[2];
    const float* Wq    = (const float*)d_in[3];
    const float* Wk    = (const float*)d_in[4];
    const float* Wv    = (const float*)d_in[5];
    const float* Wo    = (const float*)d_in[6];
    const float* bo    = (const float*)d_in[7];
    const float* ln2_g = (const float*)d_in[8];
    const float* ln2_b = (const float*)d_in[9];
    const float* W1    = (const float*)d_in[10];
    const float* b1    = (const float*)d_in[11];
    const float* W2    = (const float*)d_in[12];
    const float* b2    = (const float*)d_in[13];
    const float* projW = (const float*)d_in[14];
    const float* projb = (const float*)d_in[15];
    float* out = (float*)d_out;

    float *X, *QKV, *pbuf, *colmax, *colinv, *ctx;
    __half *Hhi, *Hlo, *Ghi, *Glo, *Whi, *Wlo;
    cudaGetSymbolAddress((void**)&X, g_X);
    cudaGetSymbolAddress((void**)&QKV, g_QKV);
    cudaGetSymbolAddress((void**)&Hhi, g_Hhi);
    cudaGetSymbolAddress((void**)&Hlo, g_Hlo);
    cudaGetSymbolAddress((void**)&Ghi, g_Ghi);
    cudaGetSymbolAddress((void**)&Glo, g_Glo);
    cudaGetSymbolAddress((void**)&Whi, g_Whi);
    cudaGetSymbolAddress((void**)&Wlo, g_Wlo);
    cudaGetSymbolAddress((void**)&pbuf, g_pbuf);
    cudaGetSymbolAddress((void**)&colmax, g_colmax);
    cudaGetSymbolAddress((void**)&colinv, g_colinv);
    cudaGetSymbolAddress((void**)&ctx, g_ctx);

    cudaFuncSetAttribute(hgemm<0>, cudaFuncAttributeMaxDynamicSharedMemorySize, GEMM_SMEM);
    cudaFuncSetAttribute(hgemm<1>, cudaFuncAttributeMaxDynamicSharedMemorySize, GEMM_SMEM);
    cudaFuncSetAttribute(hgemm<2>, cudaFuncAttributeMaxDynamicSharedMemorySize, GEMM_SMEM);
    cudaFuncSetAttribute(hgemm<3>, cudaFuncAttributeMaxDynamicSharedMemorySize, GEMM_SMEM);

    pe_kernel<<<NSEQ * DIM / 256, 256>>>(x, X);
    wsplit_kernel<<<8192, 256>>>(Wq, Wk, Wv, Wo, W1, W2, projW, Whi, Wlo);

    dim3 gQKV(12, 64), gDD(4, 64), gFF(16, 64), gLL(32, 64);
    dim3 gctx(HEADS, 16), go(NSEQ / 64, HEADS);

    for (int l = 0; l < 2; l++) {
        ln_kernel<<<NSEQ, 128>>>(X, ln1_g + l * DIM, ln1_b + l * DIM, Hhi, Hlo);
        // fused Q|K|V: weight rows for j=0,1,2 are contiguous in the table
        hgemm<0><<<gQKV, 256, GEMM_SMEM>>>(Hhi, Hlo, Whi + WOFF_QKVO(l, 0), Wlo + WOFF_QKVO(l, 0),
                                           QKV, nullptr, nullptr, nullptr, nullptr, 512, QKVS);

        qsoftmax_kernel<<<NSEQ, 256>>>(QKV);
        kcolmax_kernel<<<64, 512>>>(QKV + 512, pbuf);
        kcolmax_reduce<<<1, 512>>>(pbuf, colmax);
        kexp_kernel<<<64, 512>>>(QKV + 512, colmax, pbuf);
        kcolsum_reduce<<<1, 512>>>(pbuf, colinv);
        ctx_zero_kernel<<<HEADS * DH * DH / 256, 256>>>(ctx);
        ctx_kernel<<<gctx, 256>>>(QKV + 512, QKV + 1024, ctx);
        ctx_fix_kernel<<<HEADS * DH * DH / 256, 256>>>(ctx, colinv);
        attn_o_kernel<<<go, 256>>>(QKV, ctx, Hhi, Hlo);

        hgemm<2><<<gDD, 256, GEMM_SMEM>>>(Hhi, Hlo, Whi + WOFF_QKVO(l, 3), Wlo + WOFF_QKVO(l, 3),
                                          X, nullptr, nullptr, bo + l * DIM, X, 512, 512);

        ln_kernel<<<NSEQ, 128>>>(X, ln2_g + l * DIM, ln2_b + l * DIM, Hhi, Hlo);
        hgemm<3><<<gFF, 256, GEMM_SMEM>>>(Hhi, Hlo, Whi + WOFF_W1(l), Wlo + WOFF_W1(l),
                                          nullptr, Ghi, Glo, b1 + l * FFD, nullptr, 512, 2048);
        hgemm<2><<<gDD, 256, GEMM_SMEM>>>(Ghi, Glo, Whi + WOFF_W2(l), Wlo + WOFF_W2(l),
                                          X, nullptr, nullptr, b2 + l * DIM, X, 2048, 512);
    }

    split_kernel<<<NSEQ * DIM / 1024, 256>>>(X, Hhi, Hlo);
    hgemm<1><<<gLL, 256, GEMM_SMEM>>>(Hhi, Hlo, Whi + WOFF_PJ, Wlo + WOFF_PJ,
                                      out, nullptr, nullptr, projb, nullptr, 512, 4096);
}